// round 12
// baseline (speedup 1.0000x reference)
#include <cuda_runtime.h>
#include <cuda_fp16.h>
#include <math.h>
#include <stdint.h>

#define DIMC   2048
#define NH     16
#define NKV    4
#define SEQ    2048
#define BATCH  2
#define HD     128
#define QKVW   3072   // NH*HD + 2*NKV*HD

// ---------------- scratch (static device memory; no allocs) ----------------
__device__ float g_qkv[BATCH*SEQ*QKVW];
__device__ __half g_xh[BATCH*SEQ*DIMC];
__device__ __half g_xl[BATCH*SEQ*DIMC];
__device__ __half g_attnh[BATCH*SEQ*NH*HD];
__device__ __half g_attnl[BATCH*SEQ*NH*HD];
__device__ __half g_qkvWh[QKVW*DIMC];      // [3072][2048] (WqT;WkT;WvT) fp16
__device__ __half g_WoTh[DIMC*DIMC];
__device__ __half g_Qh[BATCH*NH*SEQ*HD];
__device__ __half g_Ql[BATCH*NH*SEQ*HD];
__device__ __half g_Kh[BATCH*NKV*SEQ*HD];
__device__ __half g_Vh[BATCH*NKV*HD*SEQ];

// ================= helpers =================
__device__ __forceinline__ void mma16(float* c, const uint32_t* a, const uint32_t* b) {
    asm volatile(
        "mma.sync.aligned.m16n8k16.row.col.f32.f16.f16.f32 "
        "{%0,%1,%2,%3}, {%4,%5,%6,%7}, {%8,%9}, {%0,%1,%2,%3};"
        : "+f"(c[0]), "+f"(c[1]), "+f"(c[2]), "+f"(c[3])
        : "r"(a[0]), "r"(a[1]), "r"(a[2]), "r"(a[3]), "r"(b[0]), "r"(b[1]));
}
__device__ __forceinline__ void split2h(float x, float y, uint32_t& h, uint32_t& l) {
    __half2 hh = __floats2half2_rn(x, y);
    float rx = x - __half2float(__low2half(hh));
    float ry = y - __half2float(__high2half(hh));
    __half2 ll = __floats2half2_rn(rx, ry);
    h = *reinterpret_cast<uint32_t*>(&hh);
    l = *reinterpret_cast<uint32_t*>(&ll);
}
__device__ __forceinline__ void ldsm4(uint32_t* r, uint32_t addr) {
    asm volatile("ldmatrix.sync.aligned.m8n8.x4.shared.b16 {%0,%1,%2,%3}, [%4];"
                 : "=r"(r[0]), "=r"(r[1]), "=r"(r[2]), "=r"(r[3]) : "r"(addr));
}
__device__ __forceinline__ void cpasync16(uint32_t dst, const void* src) {
    asm volatile("cp.async.cg.shared.global [%0], [%1], 16;" :: "r"(dst), "l"(src));
}
__device__ __forceinline__ void cp_commit() { asm volatile("cp.async.commit_group;"); }
__device__ __forceinline__ void cp_wait1() { asm volatile("cp.async.wait_group 1;"); }
__device__ __forceinline__ void cp_wait0() { asm volatile("cp.async.wait_group 0;"); }

// ================= fp16x2 GEMM: BK=64, 2-stage cp.async, 2 CTAs/SM =========
// C = A @ Bt^T, A = Ah+Al (fp16 hi/lo), B single fp16.
// 128x128 tile, BK=64, 256 thr (8 warps 4x2), warp tile 32x64, 1 sync/chunk.
// B fragments double-buffered across jp to hide LDSM latency under MMAs.
#define PSTR   72                    // 64 data + 8 pad (144B rows, conflict-free)
#define TILE_A (128 * PSTR)          // 9216 elems per tensor per stage
#define STGE   (3 * TILE_A)          // elems per stage (Ah, Al, B)
#define GEMM_SMEM (2 * STGE * 2)     // 110592 B (2 stages)

__global__ void __launch_bounds__(256, 2) gemm_ps(
        const __half* __restrict__ Ah, const __half* __restrict__ Al,
        const __half* __restrict__ Bh,
        float* __restrict__ C, int N, int K) {
    extern __shared__ __align__(16) __half sm[];
    const uint32_t sbase = (uint32_t)__cvta_generic_to_shared(sm);

    const int t = threadIdx.x;
    const int wid = t >> 5, lane = t & 31;
    const int g = lane >> 2, tig = lane & 3;
    const int wm = wid & 3, wn = wid >> 2;
    const int m0w = wm * 32, n0w = wn * 64;
    const int row0 = blockIdx.y * 128, col0 = blockIdx.x * 128;

    const int tk = t & 7, tm = t >> 3;
    const __half* Agh = Ah + (size_t)(row0 + tm) * K + tk * 8;
    const __half* Agl = Al + (size_t)(row0 + tm) * K + tk * 8;
    const __half* Bgh = Bh + (size_t)(col0 + tm) * K + tk * 8;
    const uint32_t doff = (uint32_t)(tm * PSTR + tk * 8) * 2;

    // per-warp B fragment smem row/col pieces (jp-dependent row)
    const int brow_base = n0w + (lane & 7) + ((lane >> 4) & 1) * 8;
    const int bcol_half = ((lane >> 3) & 1) * 8;
    // per-warp A fragment addressing
    const int arow_lane = lane & 15;
    const int acol_half = (lane >> 4) << 3;

    float acc[2][8][4];
#pragma unroll
    for (int mf = 0; mf < 2; mf++)
#pragma unroll
        for (int nf = 0; nf < 8; nf++)
#pragma unroll
            for (int e = 0; e < 4; e++) acc[mf][nf][e] = 0.f;

    const int CH = K / 64;
    auto issue = [&](int c) {
        const int s = c & 1;
        const int k0 = c * 64;
        uint32_t b0 = sbase + (uint32_t)(s * STGE) * 2 + doff;
#pragma unroll
        for (int rp = 0; rp < 4; rp++) {
            uint32_t ro = (uint32_t)(32 * rp * PSTR) * 2;
            size_t go = k0 + (size_t)(32 * rp) * K;
            cpasync16(b0 + ro, Agh + go);
            cpasync16(b0 + (uint32_t)TILE_A * 2 + ro, Agl + go);
            cpasync16(b0 + (uint32_t)(2 * TILE_A) * 2 + ro, Bgh + go);
        }
        cp_commit();
    };

    issue(0);

    for (int c = 0; c < CH; c++) {
        cp_wait0();
        __syncthreads();
        if (c + 1 < CH) issue(c + 1);
        const uint32_t base = sbase + (uint32_t)((c & 1) * STGE) * 2;

#pragma unroll
        for (int kk = 0; kk < 4; kk++) {
            // A fragments (once per kk)
            uint32_t ah[2][4], al[2][4];
#pragma unroll
            for (int mf = 0; mf < 2; mf++) {
                int rowA = m0w + mf * 16 + arow_lane;
                int colA = kk * 16 + acol_half;
                uint32_t aA = base + (uint32_t)(rowA * PSTR + colA) * 2;
                ldsm4(ah[mf], aA);
                ldsm4(al[mf], aA + (uint32_t)TILE_A * 2);
            }
            // B fragments: double-buffered across jp
            uint32_t bh[2][4];
            {
                int rowB = brow_base;            // jp = 0
                int colB = kk * 16 + bcol_half;
                ldsm4(bh[0], base + (uint32_t)(2 * TILE_A + rowB * PSTR + colB) * 2);
            }
#pragma unroll
            for (int jp = 0; jp < 4; jp++) {
                if (jp < 3) {
                    int rowB = brow_base + (jp + 1) * 16;
                    int colB = kk * 16 + bcol_half;
                    ldsm4(bh[(jp + 1) & 1],
                          base + (uint32_t)(2 * TILE_A + rowB * PSTR + colB) * 2);
                }
                const uint32_t* b = bh[jp & 1];
                mma16(acc[0][2 * jp],     ah[0], b);
                mma16(acc[0][2 * jp + 1], ah[0], b + 2);
                mma16(acc[1][2 * jp],     ah[1], b);
                mma16(acc[1][2 * jp + 1], ah[1], b + 2);
                mma16(acc[0][2 * jp],     al[0], b);
                mma16(acc[0][2 * jp + 1], al[0], b + 2);
                mma16(acc[1][2 * jp],     al[1], b);
                mma16(acc[1][2 * jp + 1], al[1], b + 2);
            }
        }
    }

#pragma unroll
    for (int mf = 0; mf < 2; mf++)
#pragma unroll
        for (int nf = 0; nf < 8; nf++) {
            int r0 = row0 + m0w + mf * 16 + g;
            int cc = col0 + n0w + nf * 8 + 2 * tig;
            *(float2*)(C + (size_t)r0 * N + cc) = make_float2(acc[mf][nf][0], acc[mf][nf][1]);
            *(float2*)(C + (size_t)(r0 + 8) * N + cc) = make_float2(acc[mf][nf][2], acc[mf][nf][3]);
        }
}

// ---------------- elementwise f32 -> fp16 hi/lo split ------------------------
__global__ void __launch_bounds__(256) split_k(const float* __restrict__ in,
        __half* __restrict__ h, __half* __restrict__ l, int n4) {
    int i = blockIdx.x * 256 + threadIdx.x;
    if (i >= n4) return;
    float4 v = ((const float4*)in)[i];
    uint2 hh, ll;
    split2h(v.x, v.y, hh.x, ll.x);
    split2h(v.z, v.w, hh.y, ll.y);
    ((uint2*)h)[i] = hh;
    ((uint2*)l)[i] = ll;
}

// ---------------- W transpose -> single fp16 [N,K] --------------------------
__global__ void __launch_bounds__(256) transpose_half(const float* __restrict__ W,
        __half* __restrict__ Th, int K, int N) {
    __shared__ float tile[32][33];
    int n0 = blockIdx.x * 32, k0 = blockIdx.y * 32;
    int tx = threadIdx.x & 31, ty = threadIdx.x >> 5;
#pragma unroll
    for (int i = ty; i < 32; i += 8)
        tile[i][tx] = W[(size_t)(k0 + i) * N + n0 + tx];
    __syncthreads();
#pragma unroll
    for (int i = ty; i < 32; i += 8)
        Th[(size_t)(n0 + i) * K + k0 + tx] = __float2half_rn(tile[tx][i]);
}

__global__ void __launch_bounds__(256) transpose_half2(
        const float* __restrict__ W0, const float* __restrict__ W1,
        __half* __restrict__ T0, __half* __restrict__ T1, int K, int N) {
    __shared__ float tile[32][33];
    const float* W = blockIdx.z ? W1 : W0;
    __half* Th = blockIdx.z ? T1 : T0;
    int n0 = blockIdx.x * 32, k0 = blockIdx.y * 32;
    int tx = threadIdx.x & 31, ty = threadIdx.x >> 5;
#pragma unroll
    for (int i = ty; i < 32; i += 8)
        tile[i][tx] = W[(size_t)(k0 + i) * N + n0 + tx];
    __syncthreads();
#pragma unroll
    for (int i = ty; i < 32; i += 8)
        Th[(size_t)(n0 + i) * K + k0 + tx] = __float2half_rn(tile[tx][i]);
}

// ---------------- RMSNorm + RoPE + head transpose + fp16 (split optional) --
__global__ void __launch_bounds__(256) rmsnorm_rope_k(const float* __restrict__ in,
        int instride, const float* __restrict__ g, const float* __restrict__ cs,
        const float* __restrict__ sn, __half* __restrict__ outh,
        __half* __restrict__ outl, int nh, int nrows) {
    int w = (blockIdx.x * 256 + threadIdx.x) >> 5;
    if (w >= nrows) return;
    int lane = threadIdx.x & 31;
    int h  = w % nh;
    int bs = w / nh;
    int b = bs / SEQ, s = bs % SEQ;
    int d = lane * 4;
    const float* row = in + (size_t)bs * instride + h * HD;
    float4 v = *(const float4*)(row + d);
    float ssq = v.x * v.x + v.y * v.y + v.z * v.z + v.w * v.w;
#pragma unroll
    for (int o = 16; o; o >>= 1) ssq += __shfl_xor_sync(0xffffffffu, ssq, o);
    float inv = rsqrtf(ssq * (1.f / HD) + 1e-6f);
    float4 gv = *(const float4*)(g + d);
    float y[4];
    y[0] = v.x * inv * gv.x;  y[1] = v.y * inv * gv.y;
    y[2] = v.z * inv * gv.z;  y[3] = v.w * inv * gv.w;
    float p[4];
#pragma unroll
    for (int i = 0; i < 4; i++) p[i] = __shfl_xor_sync(0xffffffffu, y[i], 16);
    float sgn = (lane < 16) ? -1.f : 1.f;
    float4 cv = *(const float4*)(cs + (size_t)s * HD + d);
    float4 sv = *(const float4*)(sn + (size_t)s * HD + d);
    float o0 = y[0] * cv.x + sgn * p[0] * sv.x;
    float o1 = y[1] * cv.y + sgn * p[1] * sv.y;
    float o2 = y[2] * cv.z + sgn * p[2] * sv.z;
    float o3 = y[3] * cv.w + sgn * p[3] * sv.w;
    uint2 h2, l2;
    split2h(o0, o1, h2.x, l2.x);
    split2h(o2, o3, h2.y, l2.y);
    size_t oidx = ((size_t)(b * nh + h) * SEQ + s) * HD + d;
    *(uint2*)(outh + oidx) = h2;
    if (outl) *(uint2*)(outl + oidx) = l2;
}

// ---------------- V transpose -> single fp16 [B, KV, HD, SEQ] ---------------
__global__ void __launch_bounds__(256) vtrans_k(const float* __restrict__ in,
        __half* __restrict__ outh) {
    __shared__ float tile[32][33];
    int s0 = blockIdx.x * 32, d0 = blockIdx.y * 32;
    int bkv = blockIdx.z;
    int b = bkv >> 2, kv = bkv & 3;
    int tx = threadIdx.x & 31, ty = threadIdx.x >> 5;
#pragma unroll
    for (int i = ty; i < 32; i += 8)
        tile[i][tx] = in[(size_t)(b * SEQ + s0 + i) * QKVW + kv * HD + d0 + tx];
    __syncthreads();
#pragma unroll
    for (int i = ty; i < 32; i += 8) {
        size_t oidx = ((size_t)bkv * HD + d0 + i) * SEQ + s0 + tx;
        outh[oidx] = __float2half_rn(tile[tx][i]);
    }
}

// ---------------- Flash attention: fp16x2, BM=128, Q in regs ---------------
#define QSTR 136
#define VSTR 72
#define KST  (64 * QSTR)
#define VST  (128 * VSTR)
#define STG_E (KST + VST)
#define OFF_V KST
#define FA_SMEM (3 * STG_E * 2)

__global__ void __launch_bounds__(256, 1) flash_mma(
        const __half* __restrict__ Qh, const __half* __restrict__ Ql,
        const __half* __restrict__ Kh, const __half* __restrict__ Vh,
        __half* __restrict__ Outh, __half* __restrict__ Outl) {
    extern __shared__ __align__(16) __half fsm[];
    const uint32_t sbase = (uint32_t)__cvta_generic_to_shared(fsm);

    const int t = threadIdx.x, w = t >> 5, lane = t & 31;
    const int g = lane >> 2, tig = lane & 3;
    const int qb = gridDim.x - 1 - blockIdx.x;
    const int h = blockIdx.y, b = blockIdx.z;
    const int kvh = h >> 2;
    const int m0 = w * 16;
    const float SC2 = 0.08838834764831845f * 1.4426950408889634f;

    const __half* Qgh = Qh + ((size_t)(b * NH + h) * SEQ + qb * 128) * HD;
    const __half* Qgl = Ql + ((size_t)(b * NH + h) * SEQ + qb * 128) * HD;
    const __half* Kbh = Kh + (size_t)(b * NKV + kvh) * SEQ * HD;
    const __half* Vbh = Vh + (size_t)(b * NKV + kvh) * HD * SEQ;

#pragma unroll
    for (int p = t; p < 128 * 16; p += 256) {
        int m = p >> 4, c8 = (p & 15) * 8;
        *(uint4*)&fsm[m * QSTR + c8] = *(const uint4*)(Qgh + (size_t)m * HD + c8);
        *(uint4*)&fsm[128 * QSTR + m * QSTR + c8] = *(const uint4*)(Qgl + (size_t)m * HD + c8);
    }
    __syncthreads();
    uint32_t qh[8][4], ql[8][4];
#pragma unroll
    for (int kk = 0; kk < 8; kk++) {
        int rowA = m0 + (lane & 15);
        int colA = kk * 16 + ((lane >> 4) << 3);
        uint32_t aA = sbase + (uint32_t)(rowA * QSTR + colA) * 2;
        ldsm4(qh[kk], aA);
        ldsm4(ql[kk], aA + (uint32_t)(128 * QSTR) * 2);
    }
    __syncthreads();

    const int nt = 2 * qb + 2;

    auto issue = [&](int jt, int st) {
        const uint32_t base = sbase + (uint32_t)(st * STG_E) * 2;
        const __half* Kth = Kbh + (size_t)jt * 64 * HD;
        const __half* Vth = Vbh + jt * 64;
#pragma unroll
        for (int i = 0; i < 4; i++) {
            int c = t + 256 * i;
            int kr = c >> 4, kc8 = (c & 15) * 8;
            cpasync16(base + (uint32_t)(kr * QSTR + kc8) * 2, Kth + (size_t)kr * HD + kc8);
            int vd = c >> 3, vc8 = (c & 7) * 8;
            cpasync16(base + (uint32_t)(OFF_V + vd * VSTR + vc8) * 2, Vth + (size_t)vd * SEQ + vc8);
        }
        cp_commit();
    };

    float o[16][4];
#pragma unroll
    for (int nf = 0; nf < 16; nf++)
#pragma unroll
        for (int e = 0; e < 4; e++) o[nf][e] = 0.f;
    float mrun0 = -INFINITY, mrun1 = -INFINITY, lrun0 = 0.f, lrun1 = 0.f;

    issue(0, 0);
    if (nt > 1) issue(1, 1);

    int st3 = 2;
    for (int jt = 0; jt < nt; jt++) {
        if (jt + 1 < nt) cp_wait1(); else cp_wait0();
        __syncthreads();
        if (jt + 2 < nt) {
            issue(jt + 2, st3);
            if (++st3 == 3) st3 = 0;
        }
        const uint32_t base = sbase + (uint32_t)((jt % 3) * STG_E) * 2;

        float s[8][4];
#pragma unroll
        for (int nf = 0; nf < 8; nf++)
#pragma unroll
            for (int e = 0; e < 4; e++) s[nf][e] = 0.f;
#pragma unroll
        for (int kk = 0; kk < 8; kk++) {
#pragma unroll
            for (int jp = 0; jp < 4; jp += 2) {
                int rowB0 = jp * 16 + (lane & 7) + ((lane >> 4) & 1) * 8;
                int colB = kk * 16 + ((lane >> 3) & 1) * 8;
                uint32_t a0 = base + (uint32_t)(rowB0 * QSTR + colB) * 2;
                uint32_t a1 = a0 + (uint32_t)(16 * QSTR) * 2;
                uint32_t bh0[4], bh1[4];
                ldsm4(bh0, a0);
                ldsm4(bh1, a1);
                mma16(s[2 * jp],     qh[kk], bh0);
                mma16(s[2 * jp + 1], qh[kk], bh0 + 2);
                mma16(s[2 * jp + 2], qh[kk], bh1);
                mma16(s[2 * jp + 3], qh[kk], bh1 + 2);
                mma16(s[2 * jp],     ql[kk], bh0);
                mma16(s[2 * jp + 1], ql[kk], bh0 + 2);
                mma16(s[2 * jp + 2], ql[kk], bh1);
                mma16(s[2 * jp + 3], ql[kk], bh1 + 2);
            }
        }

        const int rowg = qb * 128 + m0 + g;
        const bool diag = (jt >= 2 * qb);
#pragma unroll
        for (int nf = 0; nf < 8; nf++) {
            int colb = jt * 64 + nf * 8 + 2 * tig;
#pragma unroll
            for (int e = 0; e < 4; e++) {
                float v = s[nf][e] * SC2;
                if (diag && (colb + (e & 1)) > (rowg + (e >> 1) * 8)) v = -1e30f;
                s[nf][e] = v;
            }
        }
        float ml0 = -INFINITY, ml1 = -INFINITY;
#pragma unroll
        for (int nf = 0; nf < 8; nf++) {
            ml0 = fmaxf(ml0, fmaxf(s[nf][0], s[nf][1]));
            ml1 = fmaxf(ml1, fmaxf(s[nf][2], s[nf][3]));
        }
        ml0 = fmaxf(ml0, __shfl_xor_sync(0xffffffffu, ml0, 1));
        ml0 = fmaxf(ml0, __shfl_xor_sync(0xffffffffu, ml0, 2));
        ml1 = fmaxf(ml1, __shfl_xor_sync(0xffffffffu, ml1, 1));
        ml1 = fmaxf(ml1, __shfl_xor_sync(0xffffffffu, ml1, 2));
        float mn0 = fmaxf(mrun0, ml0), mn1 = fmaxf(mrun1, ml1);
        float c0 = exp2f(mrun0 - mn0), c1 = exp2f(mrun1 - mn1);
        float ls0 = 0.f, ls1 = 0.f;
#pragma unroll
        for (int nf = 0; nf < 8; nf++) {
            s[nf][0] = exp2f(s[nf][0] - mn0);
            s[nf][1] = exp2f(s[nf][1] - mn0);
            s[nf][2] = exp2f(s[nf][2] - mn1);
            s[nf][3] = exp2f(s[nf][3] - mn1);
            ls0 += s[nf][0] + s[nf][1];
            ls1 += s[nf][2] + s[nf][3];
        }
        ls0 += __shfl_xor_sync(0xffffffffu, ls0, 1);
        ls0 += __shfl_xor_sync(0xffffffffu, ls0, 2);
        ls1 += __shfl_xor_sync(0xffffffffu, ls1, 1);
        ls1 += __shfl_xor_sync(0xffffffffu, ls1, 2);
        lrun0 = lrun0 * c0 + ls0;
        lrun1 = lrun1 * c1 + ls1;
        mrun0 = mn0; mrun1 = mn1;
        if (__any_sync(0xffffffffu, (c0 < 1.f) || (c1 < 1.f))) {
#pragma unroll
            for (int nf = 0; nf < 16; nf++) {
                o[nf][0] *= c0; o[nf][1] *= c0;
                o[nf][2] *= c1; o[nf][3] *= c1;
            }
        }

        uint32_t pah[4][4], pal[4][4];
#pragma unroll
        for (int kk2 = 0; kk2 < 4; kk2++) {
            split2h(s[2*kk2][0],   s[2*kk2][1],   pah[kk2][0], pal[kk2][0]);
            split2h(s[2*kk2][2],   s[2*kk2][3],   pah[kk2][1], pal[kk2][1]);
            split2h(s[2*kk2+1][0], s[2*kk2+1][1], pah[kk2][2], pal[kk2][2]);
            split2h(s[2*kk2+1][2], s[2*kk2+1][3], pah[kk2][3], pal[kk2][3]);
        }

#pragma unroll
        for (int jp = 0; jp < 8; jp += 2) {
#pragma unroll
            for (int kk2 = 0; kk2 < 4; kk2++) {
                int rowB0 = jp * 16 + (lane & 7) + ((lane >> 4) & 1) * 8;
                int colB = kk2 * 16 + ((lane >> 3) & 1) * 8;
                uint32_t a0 = base + (uint32_t)(OFF_V + rowB0 * VSTR + colB) * 2;
                uint32_t a1 = a0 + (uint32_t)(16 * VSTR) * 2;
                uint32_t vh0[4], vh1[4];
                ldsm4(vh0, a0);
                ldsm4(vh1, a1);
                mma16(o[2 * jp],     pah[kk2], vh0);
                mma16(o[2 * jp + 1], pah[kk2], vh0 + 2);
                mma16(o[2 * jp + 2], pah[kk2], vh1);
                mma16(o[2 * jp + 3], pah[kk2], vh1 + 2);
                mma16(o[2 * jp],     pal[kk2], vh0);
                mma16(o[2 * jp + 1], pal[kk2], vh0 + 2);
                mma16(o[2 * jp + 2], pal[kk2], vh1);
                mma16(o[2 * jp + 3], pal[kk2], vh1 + 2);
            }
        }
    }

    float il0 = 1.f / lrun0, il1 = 1.f / lrun1;
    int qrow = qb * 128 + m0 + g;
    size_t base0 = (size_t)(b * SEQ + qrow) * (NH * HD) + h * HD;
    size_t base1 = base0 + (size_t)8 * (NH * HD);
#pragma unroll
    for (int nf = 0; nf < 16; nf++) {
        uint32_t hh, ll;
        split2h(o[nf][0] * il0, o[nf][1] * il0, hh, ll);
        *(uint32_t*)(Outh + base0 + nf * 8 + 2 * tig) = hh;
        *(uint32_t*)(Outl + base0 + nf * 8 + 2 * tig) = ll;
        split2h(o[nf][2] * il1, o[nf][3] * il1, hh, ll);
        *(uint32_t*)(Outh + base1 + nf * 8 + 2 * tig) = hh;
        *(uint32_t*)(Outl + base1 + nf * 8 + 2 * tig) = ll;
    }
}

// ---------------- launch -----------------------------------------------------
extern "C" void kernel_launch(void* const* d_in, const int* in_sizes, int n_in,
                              void* d_out, int out_size) {
    (void)in_sizes; (void)n_in; (void)out_size;
    const float* x  = (const float*)d_in[0];
    const float* Wq = (const float*)d_in[1];
    const float* Wk = (const float*)d_in[2];
    const float* Wv = (const float*)d_in[3];
    const float* Wo = (const float*)d_in[4];
    const float* qg = (const float*)d_in[5];
    const float* kg = (const float*)d_in[6];
    const float* cs = (const float*)d_in[7];
    const float* sn = (const float*)d_in[8];
    float* out = (float*)d_out;

    float* qkvb;
    __half *xh, *xl, *attnh, *attnl, *qkvWh, *WoTh, *Qh, *Ql, *Kh, *Vh;
    cudaGetSymbolAddress((void**)&qkvb,  g_qkv);
    cudaGetSymbolAddress((void**)&xh,    g_xh);
    cudaGetSymbolAddress((void**)&xl,    g_xl);
    cudaGetSymbolAddress((void**)&attnh, g_attnh);
    cudaGetSymbolAddress((void**)&attnl, g_attnl);
    cudaGetSymbolAddress((void**)&qkvWh, g_qkvWh);
    cudaGetSymbolAddress((void**)&WoTh,  g_WoTh);
    cudaGetSymbolAddress((void**)&Qh,    g_Qh);
    cudaGetSymbolAddress((void**)&Ql,    g_Ql);
    cudaGetSymbolAddress((void**)&Kh,    g_Kh);
    cudaGetSymbolAddress((void**)&Vh,    g_Vh);

    const int M = BATCH * SEQ;  // 4096

    cudaFuncSetAttribute(gemm_ps,   cudaFuncAttributeMaxDynamicSharedMemorySize, GEMM_SMEM);
    cudaFuncSetAttribute(flash_mma, cudaFuncAttributeMaxDynamicSharedMemorySize, FA_SMEM);

    split_k<<<(M * DIMC / 4 + 255) / 256, 256>>>(x, xh, xl, M * DIMC / 4);
    transpose_half<<<dim3(DIMC / 32, DIMC / 32), 256>>>(Wq, qkvWh, DIMC, DIMC);
    transpose_half2<<<dim3((NKV * HD) / 32, DIMC / 32, 2), 256>>>(
        Wk, Wv, qkvWh + (size_t)2048 * DIMC, qkvWh + (size_t)2560 * DIMC,
        DIMC, NKV * HD);
    gemm_ps<<<dim3(QKVW / 128, M / 128), 256, GEMM_SMEM>>>(
        xh, xl, qkvWh, qkvb, QKVW, DIMC);
    transpose_half<<<dim3(DIMC / 32, DIMC / 32), 256>>>(Wo, WoTh, DIMC, DIMC);

    rmsnorm_rope_k<<<(M * NH)  / 8, 256>>>(qkvb, QKVW, qg, cs, sn, Qh, Ql, NH,  M * NH);
    rmsnorm_rope_k<<<(M * NKV) / 8, 256>>>(qkvb + 2048, QKVW, kg, cs, sn, Kh, nullptr, NKV, M * NKV);
    vtrans_k<<<dim3(SEQ / 32, HD / 32, BATCH * NKV), 256>>>(qkvb + 2560, Vh);

    flash_mma<<<dim3(SEQ / 128, NH, BATCH), 256, FA_SMEM>>>(
        Qh, Ql, Kh, Vh, attnh, attnl);

    gemm_ps<<<dim3(DIMC / 128, M / 128), 256, GEMM_SMEM>>>(
        attnh, attnl, WoTh, out, DIMC, DIMC);
}

// round 13
// speedup vs baseline: 1.0649x; 1.0649x over previous
#include <cuda_runtime.h>
#include <cuda_fp16.h>
#include <math.h>
#include <stdint.h>

#define DIMC   2048
#define NH     16
#define NKV    4
#define SEQ    2048
#define BATCH  2
#define HD     128
#define QKVW   3072   // NH*HD + 2*NKV*HD

// ---------------- scratch (static device memory; no allocs) ----------------
__device__ float g_qkv[BATCH*SEQ*QKVW];
__device__ __half g_xh[BATCH*SEQ*DIMC];
__device__ __half g_xl[BATCH*SEQ*DIMC];
__device__ __half g_attnh[BATCH*SEQ*NH*HD];
__device__ __half g_attnl[BATCH*SEQ*NH*HD];
__device__ __half g_qkvWh[QKVW*DIMC];      // [3072][2048] (WqT;WkT;WvT) fp16
__device__ __half g_WoTh[DIMC*DIMC];
__device__ __half g_Qh[BATCH*NH*SEQ*HD];
__device__ __half g_Ql[BATCH*NH*SEQ*HD];
__device__ __half g_Kh[BATCH*NKV*SEQ*HD];
__device__ __half g_Vh[BATCH*NKV*HD*SEQ];

// ================= helpers =================
__device__ __forceinline__ void mma16(float* c, const uint32_t* a, const uint32_t* b) {
    asm volatile(
        "mma.sync.aligned.m16n8k16.row.col.f32.f16.f16.f32 "
        "{%0,%1,%2,%3}, {%4,%5,%6,%7}, {%8,%9}, {%0,%1,%2,%3};"
        : "+f"(c[0]), "+f"(c[1]), "+f"(c[2]), "+f"(c[3])
        : "r"(a[0]), "r"(a[1]), "r"(a[2]), "r"(a[3]), "r"(b[0]), "r"(b[1]));
}
__device__ __forceinline__ void split2h(float x, float y, uint32_t& h, uint32_t& l) {
    __half2 hh = __floats2half2_rn(x, y);
    float rx = x - __half2float(__low2half(hh));
    float ry = y - __half2float(__high2half(hh));
    __half2 ll = __floats2half2_rn(rx, ry);
    h = *reinterpret_cast<uint32_t*>(&hh);
    l = *reinterpret_cast<uint32_t*>(&ll);
}
__device__ __forceinline__ uint32_t pack2h(float x, float y) {
    __half2 hh = __floats2half2_rn(x, y);
    return *reinterpret_cast<uint32_t*>(&hh);
}
__device__ __forceinline__ void ldsm4(uint32_t* r, uint32_t addr) {
    asm volatile("ldmatrix.sync.aligned.m8n8.x4.shared.b16 {%0,%1,%2,%3}, [%4];"
                 : "=r"(r[0]), "=r"(r[1]), "=r"(r[2]), "=r"(r[3]) : "r"(addr));
}
__device__ __forceinline__ void cpasync16(uint32_t dst, const void* src) {
    asm volatile("cp.async.cg.shared.global [%0], [%1], 16;" :: "r"(dst), "l"(src));
}
__device__ __forceinline__ void cp_commit() { asm volatile("cp.async.commit_group;"); }
__device__ __forceinline__ void cp_wait1() { asm volatile("cp.async.wait_group 1;"); }
__device__ __forceinline__ void cp_wait0() { asm volatile("cp.async.wait_group 0;"); }

// ================= fp16x2 GEMM: BK=64, 2-stage cp.async, 2 CTAs/SM =========
// (R11 form — best measured GEMM)
#define PSTR   72
#define TILE_A (128 * PSTR)
#define STGE   (3 * TILE_A)
#define GEMM_SMEM (2 * STGE * 2)     // 110592 B

__global__ void __launch_bounds__(256, 2) gemm_ps(
        const __half* __restrict__ Ah, const __half* __restrict__ Al,
        const __half* __restrict__ Bh,
        float* __restrict__ C, int N, int K) {
    extern __shared__ __align__(16) __half sm[];
    const uint32_t sbase = (uint32_t)__cvta_generic_to_shared(sm);

    const int t = threadIdx.x;
    const int wid = t >> 5, lane = t & 31;
    const int g = lane >> 2, tig = lane & 3;
    const int wm = wid & 3, wn = wid >> 2;
    const int m0w = wm * 32, n0w = wn * 64;
    const int row0 = blockIdx.y * 128, col0 = blockIdx.x * 128;

    const int tk = t & 7, tm = t >> 3;
    const __half* Agh = Ah + (size_t)(row0 + tm) * K + tk * 8;
    const __half* Agl = Al + (size_t)(row0 + tm) * K + tk * 8;
    const __half* Bgh = Bh + (size_t)(col0 + tm) * K + tk * 8;
    const uint32_t doff = (uint32_t)(tm * PSTR + tk * 8) * 2;

    float acc[2][8][4];
#pragma unroll
    for (int mf = 0; mf < 2; mf++)
#pragma unroll
        for (int nf = 0; nf < 8; nf++)
#pragma unroll
            for (int e = 0; e < 4; e++) acc[mf][nf][e] = 0.f;

    const int CH = K / 64;
    auto issue = [&](int c) {
        const int s = c & 1;
        const int k0 = c * 64;
        uint32_t b0 = sbase + (uint32_t)(s * STGE) * 2 + doff;
#pragma unroll
        for (int rp = 0; rp < 4; rp++) {
            uint32_t ro = (uint32_t)(32 * rp * PSTR) * 2;
            size_t go = k0 + (size_t)(32 * rp) * K;
            cpasync16(b0 + ro, Agh + go);
            cpasync16(b0 + (uint32_t)TILE_A * 2 + ro, Agl + go);
            cpasync16(b0 + (uint32_t)(2 * TILE_A) * 2 + ro, Bgh + go);
        }
        cp_commit();
    };

    issue(0);

    for (int c = 0; c < CH; c++) {
        cp_wait0();
        __syncthreads();
        if (c + 1 < CH) issue(c + 1);
        const uint32_t base = sbase + (uint32_t)((c & 1) * STGE) * 2;

#pragma unroll
        for (int kk = 0; kk < 4; kk++) {
            uint32_t ah[2][4], al[2][4];
#pragma unroll
            for (int mf = 0; mf < 2; mf++) {
                int rowA = m0w + mf * 16 + (lane & 15);
                int colA = kk * 16 + ((lane >> 4) << 3);
                uint32_t aA = base + (uint32_t)(rowA * PSTR + colA) * 2;
                ldsm4(ah[mf], aA);
                ldsm4(al[mf], aA + (uint32_t)TILE_A * 2);
            }
#pragma unroll
            for (int jp = 0; jp < 4; jp++) {
                int rowB = n0w + jp * 16 + (lane & 7) + ((lane >> 4) & 1) * 8;
                int colB = kk * 16 + ((lane >> 3) & 1) * 8;
                uint32_t aB = base + (uint32_t)(2 * TILE_A + rowB * PSTR + colB) * 2;
                uint32_t bh[4];
                ldsm4(bh, aB);
                mma16(acc[0][2 * jp],     ah[0], bh);
                mma16(acc[0][2 * jp + 1], ah[0], bh + 2);
                mma16(acc[1][2 * jp],     ah[1], bh);
                mma16(acc[1][2 * jp + 1], ah[1], bh + 2);
                mma16(acc[0][2 * jp],     al[0], bh);
                mma16(acc[0][2 * jp + 1], al[0], bh + 2);
                mma16(acc[1][2 * jp],     al[1], bh);
                mma16(acc[1][2 * jp + 1], al[1], bh + 2);
            }
        }
    }

#pragma unroll
    for (int mf = 0; mf < 2; mf++)
#pragma unroll
        for (int nf = 0; nf < 8; nf++) {
            int r0 = row0 + m0w + mf * 16 + g;
            int cc = col0 + n0w + nf * 8 + 2 * tig;
            *(float2*)(C + (size_t)r0 * N + cc) = make_float2(acc[mf][nf][0], acc[mf][nf][1]);
            *(float2*)(C + (size_t)(r0 + 8) * N + cc) = make_float2(acc[mf][nf][2], acc[mf][nf][3]);
        }
}

// ---------------- elementwise f32 -> fp16 hi/lo split ------------------------
__global__ void __launch_bounds__(256) split_k(const float* __restrict__ in,
        __half* __restrict__ h, __half* __restrict__ l, int n4) {
    int i = blockIdx.x * 256 + threadIdx.x;
    if (i >= n4) return;
    float4 v = ((const float4*)in)[i];
    uint2 hh, ll;
    split2h(v.x, v.y, hh.x, ll.x);
    split2h(v.z, v.w, hh.y, ll.y);
    ((uint2*)h)[i] = hh;
    ((uint2*)l)[i] = ll;
}

// ---------------- W transpose -> single fp16 [N,K] --------------------------
__global__ void __launch_bounds__(256) transpose_half(const float* __restrict__ W,
        __half* __restrict__ Th, int K, int N) {
    __shared__ float tile[32][33];
    int n0 = blockIdx.x * 32, k0 = blockIdx.y * 32;
    int tx = threadIdx.x & 31, ty = threadIdx.x >> 5;
#pragma unroll
    for (int i = ty; i < 32; i += 8)
        tile[i][tx] = W[(size_t)(k0 + i) * N + n0 + tx];
    __syncthreads();
#pragma unroll
    for (int i = ty; i < 32; i += 8)
        Th[(size_t)(n0 + i) * K + k0 + tx] = __float2half_rn(tile[tx][i]);
}

__global__ void __launch_bounds__(256) transpose_half2(
        const float* __restrict__ W0, const float* __restrict__ W1,
        __half* __restrict__ T0, __half* __restrict__ T1, int K, int N) {
    __shared__ float tile[32][33];
    const float* W = blockIdx.z ? W1 : W0;
    __half* Th = blockIdx.z ? T1 : T0;
    int n0 = blockIdx.x * 32, k0 = blockIdx.y * 32;
    int tx = threadIdx.x & 31, ty = threadIdx.x >> 5;
#pragma unroll
    for (int i = ty; i < 32; i += 8)
        tile[i][tx] = W[(size_t)(k0 + i) * N + n0 + tx];
    __syncthreads();
#pragma unroll
    for (int i = ty; i < 32; i += 8)
        Th[(size_t)(n0 + i) * K + k0 + tx] = __float2half_rn(tile[tx][i]);
}

// ---------------- RMSNorm + RoPE + head transpose + fp16 (split optional) --
__global__ void __launch_bounds__(256) rmsnorm_rope_k(const float* __restrict__ in,
        int instride, const float* __restrict__ g, const float* __restrict__ cs,
        const float* __restrict__ sn, __half* __restrict__ outh,
        __half* __restrict__ outl, int nh, int nrows) {
    int w = (blockIdx.x * 256 + threadIdx.x) >> 5;
    if (w >= nrows) return;
    int lane = threadIdx.x & 31;
    int h  = w % nh;
    int bs = w / nh;
    int b = bs / SEQ, s = bs % SEQ;
    int d = lane * 4;
    const float* row = in + (size_t)bs * instride + h * HD;
    float4 v = *(const float4*)(row + d);
    float ssq = v.x * v.x + v.y * v.y + v.z * v.z + v.w * v.w;
#pragma unroll
    for (int o = 16; o; o >>= 1) ssq += __shfl_xor_sync(0xffffffffu, ssq, o);
    float inv = rsqrtf(ssq * (1.f / HD) + 1e-6f);
    float4 gv = *(const float4*)(g + d);
    float y[4];
    y[0] = v.x * inv * gv.x;  y[1] = v.y * inv * gv.y;
    y[2] = v.z * inv * gv.z;  y[3] = v.w * inv * gv.w;
    float p[4];
#pragma unroll
    for (int i = 0; i < 4; i++) p[i] = __shfl_xor_sync(0xffffffffu, y[i], 16);
    float sgn = (lane < 16) ? -1.f : 1.f;
    float4 cv = *(const float4*)(cs + (size_t)s * HD + d);
    float4 sv = *(const float4*)(sn + (size_t)s * HD + d);
    float o0 = y[0] * cv.x + sgn * p[0] * sv.x;
    float o1 = y[1] * cv.y + sgn * p[1] * sv.y;
    float o2 = y[2] * cv.z + sgn * p[2] * sv.z;
    float o3 = y[3] * cv.w + sgn * p[3] * sv.w;
    uint2 h2, l2;
    split2h(o0, o1, h2.x, l2.x);
    split2h(o2, o3, h2.y, l2.y);
    size_t oidx = ((size_t)(b * nh + h) * SEQ + s) * HD + d;
    *(uint2*)(outh + oidx) = h2;
    if (outl) *(uint2*)(outl + oidx) = l2;
}

// ---------------- V transpose -> single fp16 [B, KV, HD, SEQ] ---------------
__global__ void __launch_bounds__(256) vtrans_k(const float* __restrict__ in,
        __half* __restrict__ outh) {
    __shared__ float tile[32][33];
    int s0 = blockIdx.x * 32, d0 = blockIdx.y * 32;
    int bkv = blockIdx.z;
    int b = bkv >> 2, kv = bkv & 3;
    int tx = threadIdx.x & 31, ty = threadIdx.x >> 5;
#pragma unroll
    for (int i = ty; i < 32; i += 8)
        tile[i][tx] = in[(size_t)(b * SEQ + s0 + i) * QKVW + kv * HD + d0 + tx];
    __syncthreads();
#pragma unroll
    for (int i = ty; i < 32; i += 8) {
        size_t oidx = ((size_t)bkv * HD + d0 + i) * SEQ + s0 + tx;
        outh[oidx] = __float2half_rn(tile[tx][i]);
    }
}

// ---------------- Flash attention: fp16, BM=128, Q in regs -----------------
// QK: 2-term (Qh+Ql); PV: single-term (P hi only; residual ~2^-11 dropped)
#define QSTR 136
#define VSTR 72
#define KST  (64 * QSTR)
#define VST  (128 * VSTR)
#define STG_E (KST + VST)
#define OFF_V KST
#define FA_SMEM (3 * STG_E * 2)

__global__ void __launch_bounds__(256, 1) flash_mma(
        const __half* __restrict__ Qh, const __half* __restrict__ Ql,
        const __half* __restrict__ Kh, const __half* __restrict__ Vh,
        __half* __restrict__ Outh, __half* __restrict__ Outl) {
    extern __shared__ __align__(16) __half fsm[];
    const uint32_t sbase = (uint32_t)__cvta_generic_to_shared(fsm);

    const int t = threadIdx.x, w = t >> 5, lane = t & 31;
    const int g = lane >> 2, tig = lane & 3;
    const int qb = gridDim.x - 1 - blockIdx.x;
    const int h = blockIdx.y, b = blockIdx.z;
    const int kvh = h >> 2;
    const int m0 = w * 16;
    const float SC2 = 0.08838834764831845f * 1.4426950408889634f;

    const __half* Qgh = Qh + ((size_t)(b * NH + h) * SEQ + qb * 128) * HD;
    const __half* Qgl = Ql + ((size_t)(b * NH + h) * SEQ + qb * 128) * HD;
    const __half* Kbh = Kh + (size_t)(b * NKV + kvh) * SEQ * HD;
    const __half* Vbh = Vh + (size_t)(b * NKV + kvh) * HD * SEQ;

#pragma unroll
    for (int p = t; p < 128 * 16; p += 256) {
        int m = p >> 4, c8 = (p & 15) * 8;
        *(uint4*)&fsm[m * QSTR + c8] = *(const uint4*)(Qgh + (size_t)m * HD + c8);
        *(uint4*)&fsm[128 * QSTR + m * QSTR + c8] = *(const uint4*)(Qgl + (size_t)m * HD + c8);
    }
    __syncthreads();
    uint32_t qh[8][4], ql[8][4];
#pragma unroll
    for (int kk = 0; kk < 8; kk++) {
        int rowA = m0 + (lane & 15);
        int colA = kk * 16 + ((lane >> 4) << 3);
        uint32_t aA = sbase + (uint32_t)(rowA * QSTR + colA) * 2;
        ldsm4(qh[kk], aA);
        ldsm4(ql[kk], aA + (uint32_t)(128 * QSTR) * 2);
    }
    __syncthreads();

    const int nt = 2 * qb + 2;

    auto issue = [&](int jt, int st) {
        const uint32_t base = sbase + (uint32_t)(st * STG_E) * 2;
        const __half* Kth = Kbh + (size_t)jt * 64 * HD;
        const __half* Vth = Vbh + jt * 64;
#pragma unroll
        for (int i = 0; i < 4; i++) {
            int c = t + 256 * i;
            int kr = c >> 4, kc8 = (c & 15) * 8;
            cpasync16(base + (uint32_t)(kr * QSTR + kc8) * 2, Kth + (size_t)kr * HD + kc8);
            int vd = c >> 3, vc8 = (c & 7) * 8;
            cpasync16(base + (uint32_t)(OFF_V + vd * VSTR + vc8) * 2, Vth + (size_t)vd * SEQ + vc8);
        }
        cp_commit();
    };

    float o[16][4];
#pragma unroll
    for (int nf = 0; nf < 16; nf++)
#pragma unroll
        for (int e = 0; e < 4; e++) o[nf][e] = 0.f;
    float mrun0 = -INFINITY, mrun1 = -INFINITY, lrun0 = 0.f, lrun1 = 0.f;

    issue(0, 0);
    if (nt > 1) issue(1, 1);

    int st3 = 2;
    for (int jt = 0; jt < nt; jt++) {
        if (jt + 1 < nt) cp_wait1(); else cp_wait0();
        __syncthreads();
        if (jt + 2 < nt) {
            issue(jt + 2, st3);
            if (++st3 == 3) st3 = 0;
        }
        const uint32_t base = sbase + (uint32_t)((jt % 3) * STG_E) * 2;

        // ---- S = Q K^T (2-term) ----
        float s[8][4];
#pragma unroll
        for (int nf = 0; nf < 8; nf++)
#pragma unroll
            for (int e = 0; e < 4; e++) s[nf][e] = 0.f;
#pragma unroll
        for (int kk = 0; kk < 8; kk++) {
#pragma unroll
            for (int jp = 0; jp < 4; jp += 2) {
                int rowB0 = jp * 16 + (lane & 7) + ((lane >> 4) & 1) * 8;
                int colB = kk * 16 + ((lane >> 3) & 1) * 8;
                uint32_t a0 = base + (uint32_t)(rowB0 * QSTR + colB) * 2;
                uint32_t a1 = a0 + (uint32_t)(16 * QSTR) * 2;
                uint32_t bh0[4], bh1[4];
                ldsm4(bh0, a0);
                ldsm4(bh1, a1);
                mma16(s[2 * jp],     qh[kk], bh0);
                mma16(s[2 * jp + 1], qh[kk], bh0 + 2);
                mma16(s[2 * jp + 2], qh[kk], bh1);
                mma16(s[2 * jp + 3], qh[kk], bh1 + 2);
                mma16(s[2 * jp],     ql[kk], bh0);
                mma16(s[2 * jp + 1], ql[kk], bh0 + 2);
                mma16(s[2 * jp + 2], ql[kk], bh1);
                mma16(s[2 * jp + 3], ql[kk], bh1 + 2);
            }
        }

        const int rowg = qb * 128 + m0 + g;
        const bool diag = (jt >= 2 * qb);
#pragma unroll
        for (int nf = 0; nf < 8; nf++) {
            int colb = jt * 64 + nf * 8 + 2 * tig;
#pragma unroll
            for (int e = 0; e < 4; e++) {
                float v = s[nf][e] * SC2;
                if (diag && (colb + (e & 1)) > (rowg + (e >> 1) * 8)) v = -1e30f;
                s[nf][e] = v;
            }
        }
        float ml0 = -INFINITY, ml1 = -INFINITY;
#pragma unroll
        for (int nf = 0; nf < 8; nf++) {
            ml0 = fmaxf(ml0, fmaxf(s[nf][0], s[nf][1]));
            ml1 = fmaxf(ml1, fmaxf(s[nf][2], s[nf][3]));
        }
        ml0 = fmaxf(ml0, __shfl_xor_sync(0xffffffffu, ml0, 1));
        ml0 = fmaxf(ml0, __shfl_xor_sync(0xffffffffu, ml0, 2));
        ml1 = fmaxf(ml1, __shfl_xor_sync(0xffffffffu, ml1, 1));
        ml1 = fmaxf(ml1, __shfl_xor_sync(0xffffffffu, ml1, 2));
        float mn0 = fmaxf(mrun0, ml0), mn1 = fmaxf(mrun1, ml1);
        float c0 = exp2f(mrun0 - mn0), c1 = exp2f(mrun1 - mn1);
        float ls0 = 0.f, ls1 = 0.f;
#pragma unroll
        for (int nf = 0; nf < 8; nf++) {
            s[nf][0] = exp2f(s[nf][0] - mn0);
            s[nf][1] = exp2f(s[nf][1] - mn0);
            s[nf][2] = exp2f(s[nf][2] - mn1);
            s[nf][3] = exp2f(s[nf][3] - mn1);
            ls0 += s[nf][0] + s[nf][1];
            ls1 += s[nf][2] + s[nf][3];
        }
        ls0 += __shfl_xor_sync(0xffffffffu, ls0, 1);
        ls0 += __shfl_xor_sync(0xffffffffu, ls0, 2);
        ls1 += __shfl_xor_sync(0xffffffffu, ls1, 1);
        ls1 += __shfl_xor_sync(0xffffffffu, ls1, 2);
        lrun0 = lrun0 * c0 + ls0;
        lrun1 = lrun1 * c1 + ls1;
        mrun0 = mn0; mrun1 = mn1;
        if (__any_sync(0xffffffffu, (c0 < 1.f) || (c1 < 1.f))) {
#pragma unroll
            for (int nf = 0; nf < 16; nf++) {
                o[nf][0] *= c0; o[nf][1] *= c0;
                o[nf][2] *= c1; o[nf][3] *= c1;
            }
        }

        // ---- pack P into fp16 A frags (hi only; residual dropped) ----
        uint32_t pah[4][4];
#pragma unroll
        for (int kk2 = 0; kk2 < 4; kk2++) {
            pah[kk2][0] = pack2h(s[2*kk2][0],   s[2*kk2][1]);
            pah[kk2][1] = pack2h(s[2*kk2][2],   s[2*kk2][3]);
            pah[kk2][2] = pack2h(s[2*kk2+1][0], s[2*kk2+1][1]);
            pah[kk2][3] = pack2h(s[2*kk2+1][2], s[2*kk2+1][3]);
        }

        // ---- O += P @ V (single-term) ----
#pragma unroll
        for (int jp = 0; jp < 8; jp += 2) {
#pragma unroll
            for (int kk2 = 0; kk2 < 4; kk2++) {
                int rowB0 = jp * 16 + (lane & 7) + ((lane >> 4) & 1) * 8;
                int colB = kk2 * 16 + ((lane >> 3) & 1) * 8;
                uint32_t a0 = base + (uint32_t)(OFF_V + rowB0 * VSTR + colB) * 2;
                uint32_t a1 = a0 + (uint32_t)(16 * VSTR) * 2;
                uint32_t vh0[4], vh1[4];
                ldsm4(vh0, a0);
                ldsm4(vh1, a1);
                mma16(o[2 * jp],     pah[kk2], vh0);
                mma16(o[2 * jp + 1], pah[kk2], vh0 + 2);
                mma16(o[2 * jp + 2], pah[kk2], vh1);
                mma16(o[2 * jp + 3], pah[kk2], vh1 + 2);
            }
        }
    }

    float il0 = 1.f / lrun0, il1 = 1.f / lrun1;
    int qrow = qb * 128 + m0 + g;
    size_t base0 = (size_t)(b * SEQ + qrow) * (NH * HD) + h * HD;
    size_t base1 = base0 + (size_t)8 * (NH * HD);
#pragma unroll
    for (int nf = 0; nf < 16; nf++) {
        uint32_t hh, ll;
        split2h(o[nf][0] * il0, o[nf][1] * il0, hh, ll);
        *(uint32_t*)(Outh + base0 + nf * 8 + 2 * tig) = hh;
        *(uint32_t*)(Outl + base0 + nf * 8 + 2 * tig) = ll;
        split2h(o[nf][2] * il1, o[nf][3] * il1, hh, ll);
        *(uint32_t*)(Outh + base1 + nf * 8 + 2 * tig) = hh;
        *(uint32_t*)(Outl + base1 + nf * 8 + 2 * tig) = ll;
    }
}

// ---------------- launch -----------------------------------------------------
extern "C" void kernel_launch(void* const* d_in, const int* in_sizes, int n_in,
                              void* d_out, int out_size) {
    (void)in_sizes; (void)n_in; (void)out_size;
    const float* x  = (const float*)d_in[0];
    const float* Wq = (const float*)d_in[1];
    const float* Wk = (const float*)d_in[2];
    const float* Wv = (const float*)d_in[3];
    const float* Wo = (const float*)d_in[4];
    const float* qg = (const float*)d_in[5];
    const float* kg = (const float*)d_in[6];
    const float* cs = (const float*)d_in[7];
    const float* sn = (const float*)d_in[8];
    float* out = (float*)d_out;

    float* qkvb;
    __half *xh, *xl, *attnh, *attnl, *qkvWh, *WoTh, *Qh, *Ql, *Kh, *Vh;
    cudaGetSymbolAddress((void**)&qkvb,  g_qkv);
    cudaGetSymbolAddress((void**)&xh,    g_xh);
    cudaGetSymbolAddress((void**)&xl,    g_xl);
    cudaGetSymbolAddress((void**)&attnh, g_attnh);
    cudaGetSymbolAddress((void**)&attnl, g_attnl);
    cudaGetSymbolAddress((void**)&qkvWh, g_qkvWh);
    cudaGetSymbolAddress((void**)&WoTh,  g_WoTh);
    cudaGetSymbolAddress((void**)&Qh,    g_Qh);
    cudaGetSymbolAddress((void**)&Ql,    g_Ql);
    cudaGetSymbolAddress((void**)&Kh,    g_Kh);
    cudaGetSymbolAddress((void**)&Vh,    g_Vh);

    const int M = BATCH * SEQ;  // 4096

    cudaFuncSetAttribute(gemm_ps,   cudaFuncAttributeMaxDynamicSharedMemorySize, GEMM_SMEM);
    cudaFuncSetAttribute(flash_mma, cudaFuncAttributeMaxDynamicSharedMemorySize, FA_SMEM);

    split_k<<<(M * DIMC / 4 + 255) / 256, 256>>>(x, xh, xl, M * DIMC / 4);
    transpose_half<<<dim3(DIMC / 32, DIMC / 32), 256>>>(Wq, qkvWh, DIMC, DIMC);
    transpose_half2<<<dim3((NKV * HD) / 32, DIMC / 32, 2), 256>>>(
        Wk, Wv, qkvWh + (size_t)2048 * DIMC, qkvWh + (size_t)2560 * DIMC,
        DIMC, NKV * HD);
    gemm_ps<<<dim3(QKVW / 128, M / 128), 256, GEMM_SMEM>>>(
        xh, xl, qkvWh, qkvb, QKVW, DIMC);
    transpose_half<<<dim3(DIMC / 32, DIMC / 32), 256>>>(Wo, WoTh, DIMC, DIMC);

    rmsnorm_rope_k<<<(M * NH)  / 8, 256>>>(qkvb, QKVW, qg, cs, sn, Qh, Ql, NH,  M * NH);
    rmsnorm_rope_k<<<(M * NKV) / 8, 256>>>(qkvb + 2048, QKVW, kg, cs, sn, Kh, nullptr, NKV, M * NKV);
    vtrans_k<<<dim3(SEQ / 32, HD / 32, BATCH * NKV), 256>>>(qkvb + 2560, Vh);

    flash_mma<<<dim3(SEQ / 128, NH, BATCH), 256, FA_SMEM>>>(
        Qh, Ql, Kh, Vh, attnh, attnl);

    gemm_ps<<<dim3(DIMC / 128, M / 128), 256, GEMM_SMEM>>>(
        attnh, attnl, WoTh, out, DIMC, DIMC);
}

// round 14
// speedup vs baseline: 1.4417x; 1.3538x over previous
#include <cuda_runtime.h>
#include <cuda_fp16.h>
#include <math.h>
#include <stdint.h>

#define DIMC   2048
#define NH     16
#define NKV    4
#define SEQ    2048
#define BATCH  2
#define HD     128
#define QKVW   3072   // NH*HD + 2*NKV*HD

// ---------------- scratch (static device memory; no allocs) ----------------
__device__ float g_qkv[BATCH*SEQ*QKVW];
__device__ __half g_xh[BATCH*SEQ*DIMC];
__device__ __half g_attnh[BATCH*SEQ*NH*HD];
__device__ __half g_qkvWh[QKVW*DIMC];      // [3072][2048] (WqT;WkT;WvT) fp16
__device__ __half g_WoTh[DIMC*DIMC];
__device__ __half g_Qh[BATCH*NH*SEQ*HD];
__device__ __half g_Ql[BATCH*NH*SEQ*HD];
__device__ __half g_Kh[BATCH*NKV*SEQ*HD];
__device__ __half g_Vh[BATCH*NKV*HD*SEQ];

// ================= helpers =================
__device__ __forceinline__ void mma16(float* c, const uint32_t* a, const uint32_t* b) {
    asm volatile(
        "mma.sync.aligned.m16n8k16.row.col.f32.f16.f16.f32 "
        "{%0,%1,%2,%3}, {%4,%5,%6,%7}, {%8,%9}, {%0,%1,%2,%3};"
        : "+f"(c[0]), "+f"(c[1]), "+f"(c[2]), "+f"(c[3])
        : "r"(a[0]), "r"(a[1]), "r"(a[2]), "r"(a[3]), "r"(b[0]), "r"(b[1]));
}
__device__ __forceinline__ void split2h(float x, float y, uint32_t& h, uint32_t& l) {
    __half2 hh = __floats2half2_rn(x, y);
    float rx = x - __half2float(__low2half(hh));
    float ry = y - __half2float(__high2half(hh));
    __half2 ll = __floats2half2_rn(rx, ry);
    h = *reinterpret_cast<uint32_t*>(&hh);
    l = *reinterpret_cast<uint32_t*>(&ll);
}
__device__ __forceinline__ uint32_t pack2h(float x, float y) {
    __half2 hh = __floats2half2_rn(x, y);
    return *reinterpret_cast<uint32_t*>(&hh);
}
__device__ __forceinline__ void ldsm4(uint32_t* r, uint32_t addr) {
    asm volatile("ldmatrix.sync.aligned.m8n8.x4.shared.b16 {%0,%1,%2,%3}, [%4];"
                 : "=r"(r[0]), "=r"(r[1]), "=r"(r[2]), "=r"(r[3]) : "r"(addr));
}
__device__ __forceinline__ void cpasync16(uint32_t dst, const void* src) {
    asm volatile("cp.async.cg.shared.global [%0], [%1], 16;" :: "r"(dst), "l"(src));
}
__device__ __forceinline__ void cp_commit() { asm volatile("cp.async.commit_group;"); }
__device__ __forceinline__ void cp_wait1() { asm volatile("cp.async.wait_group 1;"); }
__device__ __forceinline__ void cp_wait0() { asm volatile("cp.async.wait_group 0;"); }

// ================= fp16 GEMM: BK=64, 2-stage cp.async, 2 CTAs/SM ===========
// C = A @ Bt^T, A and B single fp16.
// 128x128 tile, BK=64, 256 thr (8 warps 4x2), warp tile 32x64, 1 sync/chunk.
#define PSTR   72
#define TILE_A (128 * PSTR)          // 9216 elems per tensor per stage
#define STGE   (2 * TILE_A)          // elems per stage (A, B)
#define GEMM_SMEM (2 * STGE * 2)     // 73728 B (2 stages)

__global__ void __launch_bounds__(256, 2) gemm_h(
        const __half* __restrict__ Ah, const __half* __restrict__ Bh,
        float* __restrict__ C, int N, int K) {
    extern __shared__ __align__(16) __half sm[];
    const uint32_t sbase = (uint32_t)__cvta_generic_to_shared(sm);

    const int t = threadIdx.x;
    const int wid = t >> 5, lane = t & 31;
    const int g = lane >> 2, tig = lane & 3;
    const int wm = wid & 3, wn = wid >> 2;
    const int m0w = wm * 32, n0w = wn * 64;
    const int row0 = blockIdx.y * 128, col0 = blockIdx.x * 128;

    const int tk = t & 7, tm = t >> 3;
    const __half* Agh = Ah + (size_t)(row0 + tm) * K + tk * 8;
    const __half* Bgh = Bh + (size_t)(col0 + tm) * K + tk * 8;
    const uint32_t doff = (uint32_t)(tm * PSTR + tk * 8) * 2;

    float acc[2][8][4];
#pragma unroll
    for (int mf = 0; mf < 2; mf++)
#pragma unroll
        for (int nf = 0; nf < 8; nf++)
#pragma unroll
            for (int e = 0; e < 4; e++) acc[mf][nf][e] = 0.f;

    const int CH = K / 64;
    auto issue = [&](int c) {
        const int s = c & 1;
        const int k0 = c * 64;
        uint32_t b0 = sbase + (uint32_t)(s * STGE) * 2 + doff;
#pragma unroll
        for (int rp = 0; rp < 4; rp++) {
            uint32_t ro = (uint32_t)(32 * rp * PSTR) * 2;
            size_t go = k0 + (size_t)(32 * rp) * K;
            cpasync16(b0 + ro, Agh + go);
            cpasync16(b0 + (uint32_t)TILE_A * 2 + ro, Bgh + go);
        }
        cp_commit();
    };

    issue(0);

    for (int c = 0; c < CH; c++) {
        cp_wait0();
        __syncthreads();
        if (c + 1 < CH) issue(c + 1);
        const uint32_t base = sbase + (uint32_t)((c & 1) * STGE) * 2;

#pragma unroll
        for (int kk = 0; kk < 4; kk++) {
            uint32_t ah[2][4];
#pragma unroll
            for (int mf = 0; mf < 2; mf++) {
                int rowA = m0w + mf * 16 + (lane & 15);
                int colA = kk * 16 + ((lane >> 4) << 3);
                ldsm4(ah[mf], base + (uint32_t)(rowA * PSTR + colA) * 2);
            }
#pragma unroll
            for (int jp = 0; jp < 4; jp++) {
                int rowB = n0w + jp * 16 + (lane & 7) + ((lane >> 4) & 1) * 8;
                int colB = kk * 16 + ((lane >> 3) & 1) * 8;
                uint32_t aB = base + (uint32_t)(TILE_A + rowB * PSTR + colB) * 2;
                uint32_t bh[4];
                ldsm4(bh, aB);
                mma16(acc[0][2 * jp],     ah[0], bh);
                mma16(acc[0][2 * jp + 1], ah[0], bh + 2);
                mma16(acc[1][2 * jp],     ah[1], bh);
                mma16(acc[1][2 * jp + 1], ah[1], bh + 2);
            }
        }
    }

#pragma unroll
    for (int mf = 0; mf < 2; mf++)
#pragma unroll
        for (int nf = 0; nf < 8; nf++) {
            int r0 = row0 + m0w + mf * 16 + g;
            int cc = col0 + n0w + nf * 8 + 2 * tig;
            *(float2*)(C + (size_t)r0 * N + cc) = make_float2(acc[mf][nf][0], acc[mf][nf][1]);
            *(float2*)(C + (size_t)(r0 + 8) * N + cc) = make_float2(acc[mf][nf][2], acc[mf][nf][3]);
        }
}

// ---------------- elementwise f32 -> fp16 convert ----------------------------
__global__ void __launch_bounds__(256) convert_half(const float* __restrict__ in,
        __half* __restrict__ h, int n4) {
    int i = blockIdx.x * 256 + threadIdx.x;
    if (i >= n4) return;
    float4 v = ((const float4*)in)[i];
    uint2 hh;
    hh.x = pack2h(v.x, v.y);
    hh.y = pack2h(v.z, v.w);
    ((uint2*)h)[i] = hh;
}

// ---------------- W transpose -> single fp16 [N,K] --------------------------
__global__ void __launch_bounds__(256) transpose_half(const float* __restrict__ W,
        __half* __restrict__ Th, int K, int N) {
    __shared__ float tile[32][33];
    int n0 = blockIdx.x * 32, k0 = blockIdx.y * 32;
    int tx = threadIdx.x & 31, ty = threadIdx.x >> 5;
#pragma unroll
    for (int i = ty; i < 32; i += 8)
        tile[i][tx] = W[(size_t)(k0 + i) * N + n0 + tx];
    __syncthreads();
#pragma unroll
    for (int i = ty; i < 32; i += 8)
        Th[(size_t)(n0 + i) * K + k0 + tx] = __float2half_rn(tile[tx][i]);
}

__global__ void __launch_bounds__(256) transpose_half2(
        const float* __restrict__ W0, const float* __restrict__ W1,
        __half* __restrict__ T0, __half* __restrict__ T1, int K, int N) {
    __shared__ float tile[32][33];
    const float* W = blockIdx.z ? W1 : W0;
    __half* Th = blockIdx.z ? T1 : T0;
    int n0 = blockIdx.x * 32, k0 = blockIdx.y * 32;
    int tx = threadIdx.x & 31, ty = threadIdx.x >> 5;
#pragma unroll
    for (int i = ty; i < 32; i += 8)
        tile[i][tx] = W[(size_t)(k0 + i) * N + n0 + tx];
    __syncthreads();
#pragma unroll
    for (int i = ty; i < 32; i += 8)
        Th[(size_t)(n0 + i) * K + k0 + tx] = __float2half_rn(tile[tx][i]);
}

// ---------------- RMSNorm + RoPE + head transpose + fp16 (split optional) --
__global__ void __launch_bounds__(256) rmsnorm_rope_k(const float* __restrict__ in,
        int instride, const float* __restrict__ g, const float* __restrict__ cs,
        const float* __restrict__ sn, __half* __restrict__ outh,
        __half* __restrict__ outl, int nh, int nrows) {
    int w = (blockIdx.x * 256 + threadIdx.x) >> 5;
    if (w >= nrows) return;
    int lane = threadIdx.x & 31;
    int h  = w % nh;
    int bs = w / nh;
    int b = bs / SEQ, s = bs % SEQ;
    int d = lane * 4;
    const float* row = in + (size_t)bs * instride + h * HD;
    float4 v = *(const float4*)(row + d);
    float ssq = v.x * v.x + v.y * v.y + v.z * v.z + v.w * v.w;
#pragma unroll
    for (int o = 16; o; o >>= 1) ssq += __shfl_xor_sync(0xffffffffu, ssq, o);
    float inv = rsqrtf(ssq * (1.f / HD) + 1e-6f);
    float4 gv = *(const float4*)(g + d);
    float y[4];
    y[0] = v.x * inv * gv.x;  y[1] = v.y * inv * gv.y;
    y[2] = v.z * inv * gv.z;  y[3] = v.w * inv * gv.w;
    float p[4];
#pragma unroll
    for (int i = 0; i < 4; i++) p[i] = __shfl_xor_sync(0xffffffffu, y[i], 16);
    float sgn = (lane < 16) ? -1.f : 1.f;
    float4 cv = *(const float4*)(cs + (size_t)s * HD + d);
    float4 sv = *(const float4*)(sn + (size_t)s * HD + d);
    float o0 = y[0] * cv.x + sgn * p[0] * sv.x;
    float o1 = y[1] * cv.y + sgn * p[1] * sv.y;
    float o2 = y[2] * cv.z + sgn * p[2] * sv.z;
    float o3 = y[3] * cv.w + sgn * p[3] * sv.w;
    uint2 h2, l2;
    split2h(o0, o1, h2.x, l2.x);
    split2h(o2, o3, h2.y, l2.y);
    size_t oidx = ((size_t)(b * nh + h) * SEQ + s) * HD + d;
    *(uint2*)(outh + oidx) = h2;
    if (outl) *(uint2*)(outl + oidx) = l2;
}

// ---------------- V transpose -> single fp16 [B, KV, HD, SEQ] ---------------
__global__ void __launch_bounds__(256) vtrans_k(const float* __restrict__ in,
        __half* __restrict__ outh) {
    __shared__ float tile[32][33];
    int s0 = blockIdx.x * 32, d0 = blockIdx.y * 32;
    int bkv = blockIdx.z;
    int b = bkv >> 2, kv = bkv & 3;
    int tx = threadIdx.x & 31, ty = threadIdx.x >> 5;
#pragma unroll
    for (int i = ty; i < 32; i += 8)
        tile[i][tx] = in[(size_t)(b * SEQ + s0 + i) * QKVW + kv * HD + d0 + tx];
    __syncthreads();
#pragma unroll
    for (int i = ty; i < 32; i += 8) {
        size_t oidx = ((size_t)bkv * HD + d0 + i) * SEQ + s0 + tx;
        outh[oidx] = __float2half_rn(tile[tx][i]);
    }
}

// ---------------- Flash attention: fp16, BM=128, Q in regs -----------------
// QK: 2-term (Qh+Ql); PV: single-term; output single fp16
#define QSTR 136
#define VSTR 72
#define KST  (64 * QSTR)
#define VST  (128 * VSTR)
#define STG_E (KST + VST)
#define OFF_V KST
#define FA_SMEM (3 * STG_E * 2)

__global__ void __launch_bounds__(256, 1) flash_mma(
        const __half* __restrict__ Qh, const __half* __restrict__ Ql,
        const __half* __restrict__ Kh, const __half* __restrict__ Vh,
        __half* __restrict__ Outh) {
    extern __shared__ __align__(16) __half fsm[];
    const uint32_t sbase = (uint32_t)__cvta_generic_to_shared(fsm);

    const int t = threadIdx.x, w = t >> 5, lane = t & 31;
    const int g = lane >> 2, tig = lane & 3;
    const int qb = gridDim.x - 1 - blockIdx.x;
    const int h = blockIdx.y, b = blockIdx.z;
    const int kvh = h >> 2;
    const int m0 = w * 16;
    const float SC2 = 0.08838834764831845f * 1.4426950408889634f;

    const __half* Qgh = Qh + ((size_t)(b * NH + h) * SEQ + qb * 128) * HD;
    const __half* Qgl = Ql + ((size_t)(b * NH + h) * SEQ + qb * 128) * HD;
    const __half* Kbh = Kh + (size_t)(b * NKV + kvh) * SEQ * HD;
    const __half* Vbh = Vh + (size_t)(b * NKV + kvh) * HD * SEQ;

#pragma unroll
    for (int p = t; p < 128 * 16; p += 256) {
        int m = p >> 4, c8 = (p & 15) * 8;
        *(uint4*)&fsm[m * QSTR + c8] = *(const uint4*)(Qgh + (size_t)m * HD + c8);
        *(uint4*)&fsm[128 * QSTR + m * QSTR + c8] = *(const uint4*)(Qgl + (size_t)m * HD + c8);
    }
    __syncthreads();
    uint32_t qh[8][4], ql[8][4];
#pragma unroll
    for (int kk = 0; kk < 8; kk++) {
        int rowA = m0 + (lane & 15);
        int colA = kk * 16 + ((lane >> 4) << 3);
        uint32_t aA = sbase + (uint32_t)(rowA * QSTR + colA) * 2;
        ldsm4(qh[kk], aA);
        ldsm4(ql[kk], aA + (uint32_t)(128 * QSTR) * 2);
    }
    __syncthreads();

    const int nt = 2 * qb + 2;

    auto issue = [&](int jt, int st) {
        const uint32_t base = sbase + (uint32_t)(st * STG_E) * 2;
        const __half* Kth = Kbh + (size_t)jt * 64 * HD;
        const __half* Vth = Vbh + jt * 64;
#pragma unroll
        for (int i = 0; i < 4; i++) {
            int c = t + 256 * i;
            int kr = c >> 4, kc8 = (c & 15) * 8;
            cpasync16(base + (uint32_t)(kr * QSTR + kc8) * 2, Kth + (size_t)kr * HD + kc8);
            int vd = c >> 3, vc8 = (c & 7) * 8;
            cpasync16(base + (uint32_t)(OFF_V + vd * VSTR + vc8) * 2, Vth + (size_t)vd * SEQ + vc8);
        }
        cp_commit();
    };

    float o[16][4];
#pragma unroll
    for (int nf = 0; nf < 16; nf++)
#pragma unroll
        for (int e = 0; e < 4; e++) o[nf][e] = 0.f;
    float mrun0 = -INFINITY, mrun1 = -INFINITY, lrun0 = 0.f, lrun1 = 0.f;

    issue(0, 0);
    if (nt > 1) issue(1, 1);

    int st3 = 2;
    for (int jt = 0; jt < nt; jt++) {
        if (jt + 1 < nt) cp_wait1(); else cp_wait0();
        __syncthreads();
        if (jt + 2 < nt) {
            issue(jt + 2, st3);
            if (++st3 == 3) st3 = 0;
        }
        const uint32_t base = sbase + (uint32_t)((jt % 3) * STG_E) * 2;

        // ---- S = Q K^T (2-term) ----
        float s[8][4];
#pragma unroll
        for (int nf = 0; nf < 8; nf++)
#pragma unroll
            for (int e = 0; e < 4; e++) s[nf][e] = 0.f;
#pragma unroll
        for (int kk = 0; kk < 8; kk++) {
#pragma unroll
            for (int jp = 0; jp < 4; jp += 2) {
                int rowB0 = jp * 16 + (lane & 7) + ((lane >> 4) & 1) * 8;
                int colB = kk * 16 + ((lane >> 3) & 1) * 8;
                uint32_t a0 = base + (uint32_t)(rowB0 * QSTR + colB) * 2;
                uint32_t a1 = a0 + (uint32_t)(16 * QSTR) * 2;
                uint32_t bh0[4], bh1[4];
                ldsm4(bh0, a0);
                ldsm4(bh1, a1);
                mma16(s[2 * jp],     qh[kk], bh0);
                mma16(s[2 * jp + 1], qh[kk], bh0 + 2);
                mma16(s[2 * jp + 2], qh[kk], bh1);
                mma16(s[2 * jp + 3], qh[kk], bh1 + 2);
                mma16(s[2 * jp],     ql[kk], bh0);
                mma16(s[2 * jp + 1], ql[kk], bh0 + 2);
                mma16(s[2 * jp + 2], ql[kk], bh1);
                mma16(s[2 * jp + 3], ql[kk], bh1 + 2);
            }
        }

        const int rowg = qb * 128 + m0 + g;
        const bool diag = (jt >= 2 * qb);
#pragma unroll
        for (int nf = 0; nf < 8; nf++) {
            int colb = jt * 64 + nf * 8 + 2 * tig;
#pragma unroll
            for (int e = 0; e < 4; e++) {
                float v = s[nf][e] * SC2;
                if (diag && (colb + (e & 1)) > (rowg + (e >> 1) * 8)) v = -1e30f;
                s[nf][e] = v;
            }
        }
        float ml0 = -INFINITY, ml1 = -INFINITY;
#pragma unroll
        for (int nf = 0; nf < 8; nf++) {
            ml0 = fmaxf(ml0, fmaxf(s[nf][0], s[nf][1]));
            ml1 = fmaxf(ml1, fmaxf(s[nf][2], s[nf][3]));
        }
        ml0 = fmaxf(ml0, __shfl_xor_sync(0xffffffffu, ml0, 1));
        ml0 = fmaxf(ml0, __shfl_xor_sync(0xffffffffu, ml0, 2));
        ml1 = fmaxf(ml1, __shfl_xor_sync(0xffffffffu, ml1, 1));
        ml1 = fmaxf(ml1, __shfl_xor_sync(0xffffffffu, ml1, 2));
        float mn0 = fmaxf(mrun0, ml0), mn1 = fmaxf(mrun1, ml1);
        float c0 = exp2f(mrun0 - mn0), c1 = exp2f(mrun1 - mn1);
        float ls0 = 0.f, ls1 = 0.f;
#pragma unroll
        for (int nf = 0; nf < 8; nf++) {
            s[nf][0] = exp2f(s[nf][0] - mn0);
            s[nf][1] = exp2f(s[nf][1] - mn0);
            s[nf][2] = exp2f(s[nf][2] - mn1);
            s[nf][3] = exp2f(s[nf][3] - mn1);
            ls0 += s[nf][0] + s[nf][1];
            ls1 += s[nf][2] + s[nf][3];
        }
        ls0 += __shfl_xor_sync(0xffffffffu, ls0, 1);
        ls0 += __shfl_xor_sync(0xffffffffu, ls0, 2);
        ls1 += __shfl_xor_sync(0xffffffffu, ls1, 1);
        ls1 += __shfl_xor_sync(0xffffffffu, ls1, 2);
        lrun0 = lrun0 * c0 + ls0;
        lrun1 = lrun1 * c1 + ls1;
        mrun0 = mn0; mrun1 = mn1;
        if (__any_sync(0xffffffffu, (c0 < 1.f) || (c1 < 1.f))) {
#pragma unroll
            for (int nf = 0; nf < 16; nf++) {
                o[nf][0] *= c0; o[nf][1] *= c0;
                o[nf][2] *= c1; o[nf][3] *= c1;
            }
        }

        uint32_t pah[4][4];
#pragma unroll
        for (int kk2 = 0; kk2 < 4; kk2++) {
            pah[kk2][0] = pack2h(s[2*kk2][0],   s[2*kk2][1]);
            pah[kk2][1] = pack2h(s[2*kk2][2],   s[2*kk2][3]);
            pah[kk2][2] = pack2h(s[2*kk2+1][0], s[2*kk2+1][1]);
            pah[kk2][3] = pack2h(s[2*kk2+1][2], s[2*kk2+1][3]);
        }

#pragma unroll
        for (int jp = 0; jp < 8; jp += 2) {
#pragma unroll
            for (int kk2 = 0; kk2 < 4; kk2++) {
                int rowB0 = jp * 16 + (lane & 7) + ((lane >> 4) & 1) * 8;
                int colB = kk2 * 16 + ((lane >> 3) & 1) * 8;
                uint32_t a0 = base + (uint32_t)(OFF_V + rowB0 * VSTR + colB) * 2;
                uint32_t a1 = a0 + (uint32_t)(16 * VSTR) * 2;
                uint32_t vh0[4], vh1[4];
                ldsm4(vh0, a0);
                ldsm4(vh1, a1);
                mma16(o[2 * jp],     pah[kk2], vh0);
                mma16(o[2 * jp + 1], pah[kk2], vh0 + 2);
                mma16(o[2 * jp + 2], pah[kk2], vh1);
                mma16(o[2 * jp + 3], pah[kk2], vh1 + 2);
            }
        }
    }

    float il0 = 1.f / lrun0, il1 = 1.f / lrun1;
    int qrow = qb * 128 + m0 + g;
    size_t base0 = (size_t)(b * SEQ + qrow) * (NH * HD) + h * HD;
    size_t base1 = base0 + (size_t)8 * (NH * HD);
#pragma unroll
    for (int nf = 0; nf < 16; nf++) {
        *(uint32_t*)(Outh + base0 + nf * 8 + 2 * tig) = pack2h(o[nf][0] * il0, o[nf][1] * il0);
        *(uint32_t*)(Outh + base1 + nf * 8 + 2 * tig) = pack2h(o[nf][2] * il1, o[nf][3] * il1);
    }
}

// ---------------- launch -----------------------------------------------------
extern "C" void kernel_launch(void* const* d_in, const int* in_sizes, int n_in,
                              void* d_out, int out_size) {
    (void)in_sizes; (void)n_in; (void)out_size;
    const float* x  = (const float*)d_in[0];
    const float* Wq = (const float*)d_in[1];
    const float* Wk = (const float*)d_in[2];
    const float* Wv = (const float*)d_in[3];
    const float* Wo = (const float*)d_in[4];
    const float* qg = (const float*)d_in[5];
    const float* kg = (const float*)d_in[6];
    const float* cs = (const float*)d_in[7];
    const float* sn = (const float*)d_in[8];
    float* out = (float*)d_out;

    float* qkvb;
    __half *xh, *attnh, *qkvWh, *WoTh, *Qh, *Ql, *Kh, *Vh;
    cudaGetSymbolAddress((void**)&qkvb,  g_qkv);
    cudaGetSymbolAddress((void**)&xh,    g_xh);
    cudaGetSymbolAddress((void**)&attnh, g_attnh);
    cudaGetSymbolAddress((void**)&qkvWh, g_qkvWh);
    cudaGetSymbolAddress((void**)&WoTh,  g_WoTh);
    cudaGetSymbolAddress((void**)&Qh,    g_Qh);
    cudaGetSymbolAddress((void**)&Ql,    g_Ql);
    cudaGetSymbolAddress((void**)&Kh,    g_Kh);
    cudaGetSymbolAddress((void**)&Vh,    g_Vh);

    const int M = BATCH * SEQ;  // 4096

    cudaFuncSetAttribute(gemm_h,    cudaFuncAttributeMaxDynamicSharedMemorySize, GEMM_SMEM);
    cudaFuncSetAttribute(flash_mma, cudaFuncAttributeMaxDynamicSharedMemorySize, FA_SMEM);

    convert_half<<<(M * DIMC / 4 + 255) / 256, 256>>>(x, xh, M * DIMC / 4);
    transpose_half<<<dim3(DIMC / 32, DIMC / 32), 256>>>(Wq, qkvWh, DIMC, DIMC);
    transpose_half2<<<dim3((NKV * HD) / 32, DIMC / 32, 2), 256>>>(
        Wk, Wv, qkvWh + (size_t)2048 * DIMC, qkvWh + (size_t)2560 * DIMC,
        DIMC, NKV * HD);
    gemm_h<<<dim3(QKVW / 128, M / 128), 256, GEMM_SMEM>>>(
        xh, qkvWh, qkvb, QKVW, DIMC);
    transpose_half<<<dim3(DIMC / 32, DIMC / 32), 256>>>(Wo, WoTh, DIMC, DIMC);

    rmsnorm_rope_k<<<(M * NH)  / 8, 256>>>(qkvb, QKVW, qg, cs, sn, Qh, Ql, NH,  M * NH);
    rmsnorm_rope_k<<<(M * NKV) / 8, 256>>>(qkvb + 2048, QKVW, kg, cs, sn, Kh, nullptr, NKV, M * NKV);
    vtrans_k<<<dim3(SEQ / 32, HD / 32, BATCH * NKV), 256>>>(qkvb + 2560, Vh);

    flash_mma<<<dim3(SEQ / 128, NH, BATCH), 256, FA_SMEM>>>(
        Qh, Ql, Kh, Vh, attnh);

    gemm_h<<<dim3(DIMC / 128, M / 128), 256, GEMM_SMEM>>>(
        attnh, WoTh, out, DIMC, DIMC);
}

// round 15
// speedup vs baseline: 1.5458x; 1.0722x over previous
#include <cuda_runtime.h>
#include <cuda_fp16.h>
#include <math.h>
#include <stdint.h>

#define DIMC   2048
#define NH     16
#define NKV    4
#define SEQ    2048
#define BATCH  2
#define HD     128
#define QKVW   3072   // NH*HD + 2*NKV*HD

// ---------------- scratch (static device memory; no allocs) ----------------
__device__ float g_qkv[BATCH*SEQ*QKVW];
__device__ __half g_xh[BATCH*SEQ*DIMC];
__device__ __half g_attnh[BATCH*SEQ*NH*HD];
__device__ __half g_qkvWh[QKVW*DIMC];      // [3072][2048] (WqT;WkT;WvT) fp16
__device__ __half g_WoTh[DIMC*DIMC];
__device__ __half g_Qh[BATCH*NH*SEQ*HD];
__device__ __half g_Kh[BATCH*NKV*SEQ*HD];
__device__ __half g_Vh[BATCH*NKV*HD*SEQ];

// ================= helpers =================
__device__ __forceinline__ void mma16(float* c, const uint32_t* a, const uint32_t* b) {
    asm volatile(
        "mma.sync.aligned.m16n8k16.row.col.f32.f16.f16.f32 "
        "{%0,%1,%2,%3}, {%4,%5,%6,%7}, {%8,%9}, {%0,%1,%2,%3};"
        : "+f"(c[0]), "+f"(c[1]), "+f"(c[2]), "+f"(c[3])
        : "r"(a[0]), "r"(a[1]), "r"(a[2]), "r"(a[3]), "r"(b[0]), "r"(b[1]));
}
__device__ __forceinline__ uint32_t pack2h(float x, float y) {
    __half2 hh = __floats2half2_rn(x, y);
    return *reinterpret_cast<uint32_t*>(&hh);
}
__device__ __forceinline__ void ldsm4(uint32_t* r, uint32_t addr) {
    asm volatile("ldmatrix.sync.aligned.m8n8.x4.shared.b16 {%0,%1,%2,%3}, [%4];"
                 : "=r"(r[0]), "=r"(r[1]), "=r"(r[2]), "=r"(r[3]) : "r"(addr));
}
__device__ __forceinline__ void cpasync16(uint32_t dst, const void* src) {
    asm volatile("cp.async.cg.shared.global [%0], [%1], 16;" :: "r"(dst), "l"(src));
}
__device__ __forceinline__ void cp_commit() { asm volatile("cp.async.commit_group;"); }
__device__ __forceinline__ void cp_wait1() { asm volatile("cp.async.wait_group 1;"); }
__device__ __forceinline__ void cp_wait0() { asm volatile("cp.async.wait_group 0;"); }

// ================= fp16 GEMM: BK=64, 2-stage cp.async, 2 CTAs/SM ===========
#define PSTR   72
#define TILE_A (128 * PSTR)
#define STGE   (2 * TILE_A)
#define GEMM_SMEM (2 * STGE * 2)     // 73728 B

__global__ void __launch_bounds__(256, 2) gemm_h(
        const __half* __restrict__ Ah, const __half* __restrict__ Bh,
        float* __restrict__ C, int N, int K) {
    extern __shared__ __align__(16) __half sm[];
    const uint32_t sbase = (uint32_t)__cvta_generic_to_shared(sm);

    const int t = threadIdx.x;
    const int wid = t >> 5, lane = t & 31;
    const int g = lane >> 2, tig = lane & 3;
    const int wm = wid & 3, wn = wid >> 2;
    const int m0w = wm * 32, n0w = wn * 64;
    const int row0 = blockIdx.y * 128, col0 = blockIdx.x * 128;

    const int tk = t & 7, tm = t >> 3;
    const __half* Agh = Ah + (size_t)(row0 + tm) * K + tk * 8;
    const __half* Bgh = Bh + (size_t)(col0 + tm) * K + tk * 8;
    const uint32_t doff = (uint32_t)(tm * PSTR + tk * 8) * 2;

    float acc[2][8][4];
#pragma unroll
    for (int mf = 0; mf < 2; mf++)
#pragma unroll
        for (int nf = 0; nf < 8; nf++)
#pragma unroll
            for (int e = 0; e < 4; e++) acc[mf][nf][e] = 0.f;

    const int CH = K / 64;
    auto issue = [&](int c) {
        const int s = c & 1;
        const int k0 = c * 64;
        uint32_t b0 = sbase + (uint32_t)(s * STGE) * 2 + doff;
#pragma unroll
        for (int rp = 0; rp < 4; rp++) {
            uint32_t ro = (uint32_t)(32 * rp * PSTR) * 2;
            size_t go = k0 + (size_t)(32 * rp) * K;
            cpasync16(b0 + ro, Agh + go);
            cpasync16(b0 + (uint32_t)TILE_A * 2 + ro, Bgh + go);
        }
        cp_commit();
    };

    issue(0);

    for (int c = 0; c < CH; c++) {
        cp_wait0();
        __syncthreads();
        if (c + 1 < CH) issue(c + 1);
        const uint32_t base = sbase + (uint32_t)((c & 1) * STGE) * 2;

#pragma unroll
        for (int kk = 0; kk < 4; kk++) {
            uint32_t ah[2][4];
#pragma unroll
            for (int mf = 0; mf < 2; mf++) {
                int rowA = m0w + mf * 16 + (lane & 15);
                int colA = kk * 16 + ((lane >> 4) << 3);
                ldsm4(ah[mf], base + (uint32_t)(rowA * PSTR + colA) * 2);
            }
#pragma unroll
            for (int jp = 0; jp < 4; jp++) {
                int rowB = n0w + jp * 16 + (lane & 7) + ((lane >> 4) & 1) * 8;
                int colB = kk * 16 + ((lane >> 3) & 1) * 8;
                uint32_t aB = base + (uint32_t)(TILE_A + rowB * PSTR + colB) * 2;
                uint32_t bh[4];
                ldsm4(bh, aB);
                mma16(acc[0][2 * jp],     ah[0], bh);
                mma16(acc[0][2 * jp + 1], ah[0], bh + 2);
                mma16(acc[1][2 * jp],     ah[1], bh);
                mma16(acc[1][2 * jp + 1], ah[1], bh + 2);
            }
        }
    }

#pragma unroll
    for (int mf = 0; mf < 2; mf++)
#pragma unroll
        for (int nf = 0; nf < 8; nf++) {
            int r0 = row0 + m0w + mf * 16 + g;
            int cc = col0 + n0w + nf * 8 + 2 * tig;
            *(float2*)(C + (size_t)r0 * N + cc) = make_float2(acc[mf][nf][0], acc[mf][nf][1]);
            *(float2*)(C + (size_t)(r0 + 8) * N + cc) = make_float2(acc[mf][nf][2], acc[mf][nf][3]);
        }
}

// ---------------- elementwise f32 -> fp16 convert ----------------------------
__global__ void __launch_bounds__(256) convert_half(const float* __restrict__ in,
        __half* __restrict__ h, int n4) {
    int i = blockIdx.x * 256 + threadIdx.x;
    if (i >= n4) return;
    float4 v = ((const float4*)in)[i];
    uint2 hh;
    hh.x = pack2h(v.x, v.y);
    hh.y = pack2h(v.z, v.w);
    ((uint2*)h)[i] = hh;
}

// ---------------- W transpose -> single fp16 [N,K] --------------------------
__global__ void __launch_bounds__(256) transpose_half(const float* __restrict__ W,
        __half* __restrict__ Th, int K, int N) {
    __shared__ float tile[32][33];
    int n0 = blockIdx.x * 32, k0 = blockIdx.y * 32;
    int tx = threadIdx.x & 31, ty = threadIdx.x >> 5;
#pragma unroll
    for (int i = ty; i < 32; i += 8)
        tile[i][tx] = W[(size_t)(k0 + i) * N + n0 + tx];
    __syncthreads();
#pragma unroll
    for (int i = ty; i < 32; i += 8)
        Th[(size_t)(n0 + i) * K + k0 + tx] = __float2half_rn(tile[tx][i]);
}

__global__ void __launch_bounds__(256) transpose_half2(
        const float* __restrict__ W0, const float* __restrict__ W1,
        __half* __restrict__ T0, __half* __restrict__ T1, int K, int N) {
    __shared__ float tile[32][33];
    const float* W = blockIdx.z ? W1 : W0;
    __half* Th = blockIdx.z ? T1 : T0;
    int n0 = blockIdx.x * 32, k0 = blockIdx.y * 32;
    int tx = threadIdx.x & 31, ty = threadIdx.x >> 5;
#pragma unroll
    for (int i = ty; i < 32; i += 8)
        tile[i][tx] = W[(size_t)(k0 + i) * N + n0 + tx];
    __syncthreads();
#pragma unroll
    for (int i = ty; i < 32; i += 8)
        Th[(size_t)(n0 + i) * K + k0 + tx] = __float2half_rn(tile[tx][i]);
}

// ---------------- RMSNorm + RoPE + head transpose -> fp16 -------------------
__global__ void __launch_bounds__(256) rmsnorm_rope_k(const float* __restrict__ in,
        int instride, const float* __restrict__ g, const float* __restrict__ cs,
        const float* __restrict__ sn, __half* __restrict__ outh,
        int nh, int nrows) {
    int w = (blockIdx.x * 256 + threadIdx.x) >> 5;
    if (w >= nrows) return;
    int lane = threadIdx.x & 31;
    int h  = w % nh;
    int bs = w / nh;
    int b = bs / SEQ, s = bs % SEQ;
    int d = lane * 4;
    const float* row = in + (size_t)bs * instride + h * HD;
    float4 v = *(const float4*)(row + d);
    float ssq = v.x * v.x + v.y * v.y + v.z * v.z + v.w * v.w;
#pragma unroll
    for (int o = 16; o; o >>= 1) ssq += __shfl_xor_sync(0xffffffffu, ssq, o);
    float inv = rsqrtf(ssq * (1.f / HD) + 1e-6f);
    float4 gv = *(const float4*)(g + d);
    float y[4];
    y[0] = v.x * inv * gv.x;  y[1] = v.y * inv * gv.y;
    y[2] = v.z * inv * gv.z;  y[3] = v.w * inv * gv.w;
    float p[4];
#pragma unroll
    for (int i = 0; i < 4; i++) p[i] = __shfl_xor_sync(0xffffffffu, y[i], 16);
    float sgn = (lane < 16) ? -1.f : 1.f;
    float4 cv = *(const float4*)(cs + (size_t)s * HD + d);
    float4 sv = *(const float4*)(sn + (size_t)s * HD + d);
    float o0 = y[0] * cv.x + sgn * p[0] * sv.x;
    float o1 = y[1] * cv.y + sgn * p[1] * sv.y;
    float o2 = y[2] * cv.z + sgn * p[2] * sv.z;
    float o3 = y[3] * cv.w + sgn * p[3] * sv.w;
    uint2 h2;
    h2.x = pack2h(o0, o1);
    h2.y = pack2h(o2, o3);
    size_t oidx = ((size_t)(b * nh + h) * SEQ + s) * HD + d;
    *(uint2*)(outh + oidx) = h2;
}

// ---------------- V transpose -> single fp16 [B, KV, HD, SEQ] ---------------
__global__ void __launch_bounds__(256) vtrans_k(const float* __restrict__ in,
        __half* __restrict__ outh) {
    __shared__ float tile[32][33];
    int s0 = blockIdx.x * 32, d0 = blockIdx.y * 32;
    int bkv = blockIdx.z;
    int b = bkv >> 2, kv = bkv & 3;
    int tx = threadIdx.x & 31, ty = threadIdx.x >> 5;
#pragma unroll
    for (int i = ty; i < 32; i += 8)
        tile[i][tx] = in[(size_t)(b * SEQ + s0 + i) * QKVW + kv * HD + d0 + tx];
    __syncthreads();
#pragma unroll
    for (int i = ty; i < 32; i += 8) {
        size_t oidx = ((size_t)bkv * HD + d0 + i) * SEQ + s0 + tx;
        outh[oidx] = __float2half_rn(tile[tx][i]);
    }
}

// ---------------- Flash attention: all single fp16, BM=128, Q in regs ------
#define QSTR 136
#define VSTR 72
#define KST  (64 * QSTR)
#define VST  (128 * VSTR)
#define STG_E (KST + VST)
#define OFF_V KST
#define FA_SMEM (3 * STG_E * 2)

__global__ void __launch_bounds__(256, 1) flash_mma(
        const __half* __restrict__ Qh, const __half* __restrict__ Kh,
        const __half* __restrict__ Vh, __half* __restrict__ Outh) {
    extern __shared__ __align__(16) __half fsm[];
    const uint32_t sbase = (uint32_t)__cvta_generic_to_shared(fsm);

    const int t = threadIdx.x, w = t >> 5, lane = t & 31;
    const int g = lane >> 2, tig = lane & 3;
    const int qb = gridDim.x - 1 - blockIdx.x;
    const int h = blockIdx.y, b = blockIdx.z;
    const int kvh = h >> 2;
    const int m0 = w * 16;
    const float SC2 = 0.08838834764831845f * 1.4426950408889634f;

    const __half* Qgh = Qh + ((size_t)(b * NH + h) * SEQ + qb * 128) * HD;
    const __half* Kbh = Kh + (size_t)(b * NKV + kvh) * SEQ * HD;
    const __half* Vbh = Vh + (size_t)(b * NKV + kvh) * HD * SEQ;

    // stage Q (128x128) in stage-0 smem, extract fragments to registers
#pragma unroll
    for (int p = t; p < 128 * 16; p += 256) {
        int m = p >> 4, c8 = (p & 15) * 8;
        *(uint4*)&fsm[m * QSTR + c8] = *(const uint4*)(Qgh + (size_t)m * HD + c8);
    }
    __syncthreads();
    uint32_t qh[8][4];
#pragma unroll
    for (int kk = 0; kk < 8; kk++) {
        int rowA = m0 + (lane & 15);
        int colA = kk * 16 + ((lane >> 4) << 3);
        ldsm4(qh[kk], sbase + (uint32_t)(rowA * QSTR + colA) * 2);
    }
    __syncthreads();

    const int nt = 2 * qb + 2;

    auto issue = [&](int jt, int st) {
        const uint32_t base = sbase + (uint32_t)(st * STG_E) * 2;
        const __half* Kth = Kbh + (size_t)jt * 64 * HD;
        const __half* Vth = Vbh + jt * 64;
#pragma unroll
        for (int i = 0; i < 4; i++) {
            int c = t + 256 * i;
            int kr = c >> 4, kc8 = (c & 15) * 8;
            cpasync16(base + (uint32_t)(kr * QSTR + kc8) * 2, Kth + (size_t)kr * HD + kc8);
            int vd = c >> 3, vc8 = (c & 7) * 8;
            cpasync16(base + (uint32_t)(OFF_V + vd * VSTR + vc8) * 2, Vth + (size_t)vd * SEQ + vc8);
        }
        cp_commit();
    };

    float o[16][4];
#pragma unroll
    for (int nf = 0; nf < 16; nf++)
#pragma unroll
        for (int e = 0; e < 4; e++) o[nf][e] = 0.f;
    float mrun0 = -INFINITY, mrun1 = -INFINITY, lrun0 = 0.f, lrun1 = 0.f;

    issue(0, 0);
    if (nt > 1) issue(1, 1);

    int st3 = 2;
    for (int jt = 0; jt < nt; jt++) {
        if (jt + 1 < nt) cp_wait1(); else cp_wait0();
        __syncthreads();
        if (jt + 2 < nt) {
            issue(jt + 2, st3);
            if (++st3 == 3) st3 = 0;
        }
        const uint32_t base = sbase + (uint32_t)((jt % 3) * STG_E) * 2;

        // ---- S = Q K^T (single term) ----
        float s[8][4];
#pragma unroll
        for (int nf = 0; nf < 8; nf++)
#pragma unroll
            for (int e = 0; e < 4; e++) s[nf][e] = 0.f;
#pragma unroll
        for (int kk = 0; kk < 8; kk++) {
#pragma unroll
            for (int jp = 0; jp < 4; jp += 2) {
                int rowB0 = jp * 16 + (lane & 7) + ((lane >> 4) & 1) * 8;
                int colB = kk * 16 + ((lane >> 3) & 1) * 8;
                uint32_t a0 = base + (uint32_t)(rowB0 * QSTR + colB) * 2;
                uint32_t a1 = a0 + (uint32_t)(16 * QSTR) * 2;
                uint32_t bh0[4], bh1[4];
                ldsm4(bh0, a0);
                ldsm4(bh1, a1);
                mma16(s[2 * jp],     qh[kk], bh0);
                mma16(s[2 * jp + 1], qh[kk], bh0 + 2);
                mma16(s[2 * jp + 2], qh[kk], bh1);
                mma16(s[2 * jp + 3], qh[kk], bh1 + 2);
            }
        }

        const int rowg = qb * 128 + m0 + g;
        const bool diag = (jt >= 2 * qb);
#pragma unroll
        for (int nf = 0; nf < 8; nf++) {
            int colb = jt * 64 + nf * 8 + 2 * tig;
#pragma unroll
            for (int e = 0; e < 4; e++) {
                float v = s[nf][e] * SC2;
                if (diag && (colb + (e & 1)) > (rowg + (e >> 1) * 8)) v = -1e30f;
                s[nf][e] = v;
            }
        }
        float ml0 = -INFINITY, ml1 = -INFINITY;
#pragma unroll
        for (int nf = 0; nf < 8; nf++) {
            ml0 = fmaxf(ml0, fmaxf(s[nf][0], s[nf][1]));
            ml1 = fmaxf(ml1, fmaxf(s[nf][2], s[nf][3]));
        }
        ml0 = fmaxf(ml0, __shfl_xor_sync(0xffffffffu, ml0, 1));
        ml0 = fmaxf(ml0, __shfl_xor_sync(0xffffffffu, ml0, 2));
        ml1 = fmaxf(ml1, __shfl_xor_sync(0xffffffffu, ml1, 1));
        ml1 = fmaxf(ml1, __shfl_xor_sync(0xffffffffu, ml1, 2));
        float mn0 = fmaxf(mrun0, ml0), mn1 = fmaxf(mrun1, ml1);
        float c0 = exp2f(mrun0 - mn0), c1 = exp2f(mrun1 - mn1);
        float ls0 = 0.f, ls1 = 0.f;
#pragma unroll
        for (int nf = 0; nf < 8; nf++) {
            s[nf][0] = exp2f(s[nf][0] - mn0);
            s[nf][1] = exp2f(s[nf][1] - mn0);
            s[nf][2] = exp2f(s[nf][2] - mn1);
            s[nf][3] = exp2f(s[nf][3] - mn1);
            ls0 += s[nf][0] + s[nf][1];
            ls1 += s[nf][2] + s[nf][3];
        }
        ls0 += __shfl_xor_sync(0xffffffffu, ls0, 1);
        ls0 += __shfl_xor_sync(0xffffffffu, ls0, 2);
        ls1 += __shfl_xor_sync(0xffffffffu, ls1, 1);
        ls1 += __shfl_xor_sync(0xffffffffu, ls1, 2);
        lrun0 = lrun0 * c0 + ls0;
        lrun1 = lrun1 * c1 + ls1;
        mrun0 = mn0; mrun1 = mn1;
        if (__any_sync(0xffffffffu, (c0 < 1.f) || (c1 < 1.f))) {
#pragma unroll
            for (int nf = 0; nf < 16; nf++) {
                o[nf][0] *= c0; o[nf][1] *= c0;
                o[nf][2] *= c1; o[nf][3] *= c1;
            }
        }

        uint32_t pah[4][4];
#pragma unroll
        for (int kk2 = 0; kk2 < 4; kk2++) {
            pah[kk2][0] = pack2h(s[2*kk2][0],   s[2*kk2][1]);
            pah[kk2][1] = pack2h(s[2*kk2][2],   s[2*kk2][3]);
            pah[kk2][2] = pack2h(s[2*kk2+1][0], s[2*kk2+1][1]);
            pah[kk2][3] = pack2h(s[2*kk2+1][2], s[2*kk2+1][3]);
        }

#pragma unroll
        for (int jp = 0; jp < 8; jp += 2) {
#pragma unroll
            for (int kk2 = 0; kk2 < 4; kk2++) {
                int rowB0 = jp * 16 + (lane & 7) + ((lane >> 4) & 1) * 8;
                int colB = kk2 * 16 + ((lane >> 3) & 1) * 8;
                uint32_t a0 = base + (uint32_t)(OFF_V + rowB0 * VSTR + colB) * 2;
                uint32_t a1 = a0 + (uint32_t)(16 * VSTR) * 2;
                uint32_t vh0[4], vh1[4];
                ldsm4(vh0, a0);
                ldsm4(vh1, a1);
                mma16(o[2 * jp],     pah[kk2], vh0);
                mma16(o[2 * jp + 1], pah[kk2], vh0 + 2);
                mma16(o[2 * jp + 2], pah[kk2], vh1);
                mma16(o[2 * jp + 3], pah[kk2], vh1 + 2);
            }
        }
    }

    float il0 = 1.f / lrun0, il1 = 1.f / lrun1;
    int qrow = qb * 128 + m0 + g;
    size_t base0 = (size_t)(b * SEQ + qrow) * (NH * HD) + h * HD;
    size_t base1 = base0 + (size_t)8 * (NH * HD);
#pragma unroll
    for (int nf = 0; nf < 16; nf++) {
        *(uint32_t*)(Outh + base0 + nf * 8 + 2 * tig) = pack2h(o[nf][0] * il0, o[nf][1] * il0);
        *(uint32_t*)(Outh + base1 + nf * 8 + 2 * tig) = pack2h(o[nf][2] * il1, o[nf][3] * il1);
    }
}

// ---------------- launch -----------------------------------------------------
extern "C" void kernel_launch(void* const* d_in, const int* in_sizes, int n_in,
                              void* d_out, int out_size) {
    (void)in_sizes; (void)n_in; (void)out_size;
    const float* x  = (const float*)d_in[0];
    const float* Wq = (const float*)d_in[1];
    const float* Wk = (const float*)d_in[2];
    const float* Wv = (const float*)d_in[3];
    const float* Wo = (const float*)d_in[4];
    const float* qg = (const float*)d_in[5];
    const float* kg = (const float*)d_in[6];
    const float* cs = (const float*)d_in[7];
    const float* sn = (const float*)d_in[8];
    float* out = (float*)d_out;

    float* qkvb;
    __half *xh, *attnh, *qkvWh, *WoTh, *Qh, *Kh, *Vh;
    cudaGetSymbolAddress((void**)&qkvb,  g_qkv);
    cudaGetSymbolAddress((void**)&xh,    g_xh);
    cudaGetSymbolAddress((void**)&attnh, g_attnh);
    cudaGetSymbolAddress((void**)&qkvWh, g_qkvWh);
    cudaGetSymbolAddress((void**)&WoTh,  g_WoTh);
    cudaGetSymbolAddress((void**)&Qh,    g_Qh);
    cudaGetSymbolAddress((void**)&Kh,    g_Kh);
    cudaGetSymbolAddress((void**)&Vh,    g_Vh);

    const int M = BATCH * SEQ;  // 4096

    cudaFuncSetAttribute(gemm_h,    cudaFuncAttributeMaxDynamicSharedMemorySize, GEMM_SMEM);
    cudaFuncSetAttribute(flash_mma, cudaFuncAttributeMaxDynamicSharedMemorySize, FA_SMEM);

    convert_half<<<(M * DIMC / 4 + 255) / 256, 256>>>(x, xh, M * DIMC / 4);
    transpose_half<<<dim3(DIMC / 32, DIMC / 32), 256>>>(Wq, qkvWh, DIMC, DIMC);
    transpose_half2<<<dim3((NKV * HD) / 32, DIMC / 32, 2), 256>>>(
        Wk, Wv, qkvWh + (size_t)2048 * DIMC, qkvWh + (size_t)2560 * DIMC,
        DIMC, NKV * HD);
    gemm_h<<<dim3(QKVW / 128, M / 128), 256, GEMM_SMEM>>>(
        xh, qkvWh, qkvb, QKVW, DIMC);
    transpose_half<<<dim3(DIMC / 32, DIMC / 32), 256>>>(Wo, WoTh, DIMC, DIMC);

    rmsnorm_rope_k<<<(M * NH)  / 8, 256>>>(qkvb, QKVW, qg, cs, sn, Qh, NH,  M * NH);
    rmsnorm_rope_k<<<(M * NKV) / 8, 256>>>(qkvb + 2048, QKVW, kg, cs, sn, Kh, NKV, M * NKV);
    vtrans_k<<<dim3(SEQ / 32, HD / 32, BATCH * NKV), 256>>>(qkvb + 2560, Vh);

    flash_mma<<<dim3(SEQ / 128, NH, BATCH), 256, FA_SMEM>>>(Qh, Kh, Vh, attnh);

    gemm_h<<<dim3(DIMC / 128, M / 128), 256, GEMM_SMEM>>>(
        attnh, WoTh, out, DIMC, DIMC);
}

// round 16
// speedup vs baseline: 1.5542x; 1.0055x over previous
#include <cuda_runtime.h>
#include <cuda_fp16.h>
#include <math.h>
#include <stdint.h>

#define DIMC   2048
#define NH     16
#define NKV    4
#define SEQ    2048
#define BATCH  2
#define HD     128
#define QKVW   3072   // NH*HD + 2*NKV*HD

// ---------------- scratch (static device memory; no allocs) ----------------
__device__ float g_qkv[BATCH*SEQ*QKVW];
__device__ __half g_xh[BATCH*SEQ*DIMC];
__device__ __half g_attnh[BATCH*SEQ*NH*HD];
__device__ __half g_qkvWh[QKVW*DIMC];      // [3072][2048] (WqT;WkT;WvT) fp16
__device__ __half g_WoTh[DIMC*DIMC];
__device__ __half g_Qh[BATCH*NH*SEQ*HD];
__device__ __half g_Kh[BATCH*NKV*SEQ*HD];
__device__ __half g_Vh[BATCH*NKV*HD*SEQ];

// ================= helpers =================
__device__ __forceinline__ void mma16(float* c, const uint32_t* a, const uint32_t* b) {
    asm volatile(
        "mma.sync.aligned.m16n8k16.row.col.f32.f16.f16.f32 "
        "{%0,%1,%2,%3}, {%4,%5,%6,%7}, {%8,%9}, {%0,%1,%2,%3};"
        : "+f"(c[0]), "+f"(c[1]), "+f"(c[2]), "+f"(c[3])
        : "r"(a[0]), "r"(a[1]), "r"(a[2]), "r"(a[3]), "r"(b[0]), "r"(b[1]));
}
__device__ __forceinline__ uint32_t pack2h(float x, float y) {
    __half2 hh = __floats2half2_rn(x, y);
    return *reinterpret_cast<uint32_t*>(&hh);
}
__device__ __forceinline__ void ldsm4(uint32_t* r, uint32_t addr) {
    asm volatile("ldmatrix.sync.aligned.m8n8.x4.shared.b16 {%0,%1,%2,%3}, [%4];"
                 : "=r"(r[0]), "=r"(r[1]), "=r"(r[2]), "=r"(r[3]) : "r"(addr));
}
__device__ __forceinline__ void cpasync16(uint32_t dst, const void* src) {
    asm volatile("cp.async.cg.shared.global [%0], [%1], 16;" :: "r"(dst), "l"(src));
}
__device__ __forceinline__ void cp_commit() { asm volatile("cp.async.commit_group;"); }
__device__ __forceinline__ void cp_wait1() { asm volatile("cp.async.wait_group 1;"); }
__device__ __forceinline__ void cp_wait0() { asm volatile("cp.async.wait_group 0;"); }

// ================= fp16 GEMM: BK=64, 3-stage cp.async, 2 CTAs/SM ===========
// C = A @ Bt^T, single fp16 operands. 128x128 tile, 256 thr, warp tile 32x64.
// 3-stage ring + wait_group 1 => two chunks of load latency cover.
#define PSTR   72
#define TILE_A (128 * PSTR)
#define STGE   (2 * TILE_A)
#define GEMM_SMEM (3 * STGE * 2)     // 110592 B (3 stages)

__global__ void __launch_bounds__(256, 2) gemm_h(
        const __half* __restrict__ Ah, const __half* __restrict__ Bh,
        float* __restrict__ C, int N, int K) {
    extern __shared__ __align__(16) __half sm[];
    const uint32_t sbase = (uint32_t)__cvta_generic_to_shared(sm);

    const int t = threadIdx.x;
    const int wid = t >> 5, lane = t & 31;
    const int g = lane >> 2, tig = lane & 3;
    const int wm = wid & 3, wn = wid >> 2;
    const int m0w = wm * 32, n0w = wn * 64;
    const int row0 = blockIdx.y * 128, col0 = blockIdx.x * 128;

    const int tk = t & 7, tm = t >> 3;
    const __half* Agh = Ah + (size_t)(row0 + tm) * K + tk * 8;
    const __half* Bgh = Bh + (size_t)(col0 + tm) * K + tk * 8;
    const uint32_t doff = (uint32_t)(tm * PSTR + tk * 8) * 2;

    float acc[2][8][4];
#pragma unroll
    for (int mf = 0; mf < 2; mf++)
#pragma unroll
        for (int nf = 0; nf < 8; nf++)
#pragma unroll
            for (int e = 0; e < 4; e++) acc[mf][nf][e] = 0.f;

    const int CH = K / 64;
    auto issue = [&](int c, int s) {
        const int k0 = c * 64;
        uint32_t b0 = sbase + (uint32_t)(s * STGE) * 2 + doff;
#pragma unroll
        for (int rp = 0; rp < 4; rp++) {
            uint32_t ro = (uint32_t)(32 * rp * PSTR) * 2;
            size_t go = k0 + (size_t)(32 * rp) * K;
            cpasync16(b0 + ro, Agh + go);
            cpasync16(b0 + (uint32_t)TILE_A * 2 + ro, Bgh + go);
        }
        cp_commit();
    };

    issue(0, 0);
    if (CH > 1) issue(1, 1);

    int st3 = 2;      // stage for chunk c+2
    for (int c = 0; c < CH; c++) {
        if (c + 1 < CH) cp_wait1(); else cp_wait0();
        __syncthreads();
        if (c + 2 < CH) {
            issue(c + 2, st3);
            if (++st3 == 3) st3 = 0;
        }
        const uint32_t base = sbase + (uint32_t)((c % 3) * STGE) * 2;

#pragma unroll
        for (int kk = 0; kk < 4; kk++) {
            uint32_t ah[2][4];
#pragma unroll
            for (int mf = 0; mf < 2; mf++) {
                int rowA = m0w + mf * 16 + (lane & 15);
                int colA = kk * 16 + ((lane >> 4) << 3);
                ldsm4(ah[mf], base + (uint32_t)(rowA * PSTR + colA) * 2);
            }
#pragma unroll
            for (int jp = 0; jp < 4; jp++) {
                int rowB = n0w + jp * 16 + (lane & 7) + ((lane >> 4) & 1) * 8;
                int colB = kk * 16 + ((lane >> 3) & 1) * 8;
                uint32_t aB = base + (uint32_t)(TILE_A + rowB * PSTR + colB) * 2;
                uint32_t bh[4];
                ldsm4(bh, aB);
                mma16(acc[0][2 * jp],     ah[0], bh);
                mma16(acc[0][2 * jp + 1], ah[0], bh + 2);
                mma16(acc[1][2 * jp],     ah[1], bh);
                mma16(acc[1][2 * jp + 1], ah[1], bh + 2);
            }
        }
    }

#pragma unroll
    for (int mf = 0; mf < 2; mf++)
#pragma unroll
        for (int nf = 0; nf < 8; nf++) {
            int r0 = row0 + m0w + mf * 16 + g;
            int cc = col0 + n0w + nf * 8 + 2 * tig;
            *(float2*)(C + (size_t)r0 * N + cc) = make_float2(acc[mf][nf][0], acc[mf][nf][1]);
            *(float2*)(C + (size_t)(r0 + 8) * N + cc) = make_float2(acc[mf][nf][2], acc[mf][nf][3]);
        }
}

// ---------------- elementwise f32 -> fp16 convert ----------------------------
__global__ void __launch_bounds__(256) convert_half(const float* __restrict__ in,
        __half* __restrict__ h, int n4) {
    int i = blockIdx.x * 256 + threadIdx.x;
    if (i >= n4) return;
    float4 v = ((const float4*)in)[i];
    uint2 hh;
    hh.x = pack2h(v.x, v.y);
    hh.y = pack2h(v.z, v.w);
    ((uint2*)h)[i] = hh;
}

// ---------------- W transpose -> single fp16 [N,K] --------------------------
__global__ void __launch_bounds__(256) transpose_half(const float* __restrict__ W,
        __half* __restrict__ Th, int K, int N) {
    __shared__ float tile[32][33];
    int n0 = blockIdx.x * 32, k0 = blockIdx.y * 32;
    int tx = threadIdx.x & 31, ty = threadIdx.x >> 5;
#pragma unroll
    for (int i = ty; i < 32; i += 8)
        tile[i][tx] = W[(size_t)(k0 + i) * N + n0 + tx];
    __syncthreads();
#pragma unroll
    for (int i = ty; i < 32; i += 8)
        Th[(size_t)(n0 + i) * K + k0 + tx] = __float2half_rn(tile[tx][i]);
}

__global__ void __launch_bounds__(256) transpose_half2(
        const float* __restrict__ W0, const float* __restrict__ W1,
        __half* __restrict__ T0, __half* __restrict__ T1, int K, int N) {
    __shared__ float tile[32][33];
    const float* W = blockIdx.z ? W1 : W0;
    __half* Th = blockIdx.z ? T1 : T0;
    int n0 = blockIdx.x * 32, k0 = blockIdx.y * 32;
    int tx = threadIdx.x & 31, ty = threadIdx.x >> 5;
#pragma unroll
    for (int i = ty; i < 32; i += 8)
        tile[i][tx] = W[(size_t)(k0 + i) * N + n0 + tx];
    __syncthreads();
#pragma unroll
    for (int i = ty; i < 32; i += 8)
        Th[(size_t)(n0 + i) * K + k0 + tx] = __float2half_rn(tile[tx][i]);
}

// ---------------- RMSNorm + RoPE + head transpose -> fp16 -------------------
__global__ void __launch_bounds__(256) rmsnorm_rope_k(const float* __restrict__ in,
        int instride, const float* __restrict__ g, const float* __restrict__ cs,
        const float* __restrict__ sn, __half* __restrict__ outh,
        int nh, int nrows) {
    int w = (blockIdx.x * 256 + threadIdx.x) >> 5;
    if (w >= nrows) return;
    int lane = threadIdx.x & 31;
    int h  = w % nh;
    int bs = w / nh;
    int b = bs / SEQ, s = bs % SEQ;
    int d = lane * 4;
    const float* row = in + (size_t)bs * instride + h * HD;
    float4 v = *(const float4*)(row + d);
    float ssq = v.x * v.x + v.y * v.y + v.z * v.z + v.w * v.w;
#pragma unroll
    for (int o = 16; o; o >>= 1) ssq += __shfl_xor_sync(0xffffffffu, ssq, o);
    float inv = rsqrtf(ssq * (1.f / HD) + 1e-6f);
    float4 gv = *(const float4*)(g + d);
    float y[4];
    y[0] = v.x * inv * gv.x;  y[1] = v.y * inv * gv.y;
    y[2] = v.z * inv * gv.z;  y[3] = v.w * inv * gv.w;
    float p[4];
#pragma unroll
    for (int i = 0; i < 4; i++) p[i] = __shfl_xor_sync(0xffffffffu, y[i], 16);
    float sgn = (lane < 16) ? -1.f : 1.f;
    float4 cv = *(const float4*)(cs + (size_t)s * HD + d);
    float4 sv = *(const float4*)(sn + (size_t)s * HD + d);
    float o0 = y[0] * cv.x + sgn * p[0] * sv.x;
    float o1 = y[1] * cv.y + sgn * p[1] * sv.y;
    float o2 = y[2] * cv.z + sgn * p[2] * sv.z;
    float o3 = y[3] * cv.w + sgn * p[3] * sv.w;
    uint2 h2;
    h2.x = pack2h(o0, o1);
    h2.y = pack2h(o2, o3);
    size_t oidx = ((size_t)(b * nh + h) * SEQ + s) * HD + d;
    *(uint2*)(outh + oidx) = h2;
}

// ---------------- V transpose -> single fp16 [B, KV, HD, SEQ] ---------------
__global__ void __launch_bounds__(256) vtrans_k(const float* __restrict__ in,
        __half* __restrict__ outh) {
    __shared__ float tile[32][33];
    int s0 = blockIdx.x * 32, d0 = blockIdx.y * 32;
    int bkv = blockIdx.z;
    int b = bkv >> 2, kv = bkv & 3;
    int tx = threadIdx.x & 31, ty = threadIdx.x >> 5;
#pragma unroll
    for (int i = ty; i < 32; i += 8)
        tile[i][tx] = in[(size_t)(b * SEQ + s0 + i) * QKVW + kv * HD + d0 + tx];
    __syncthreads();
#pragma unroll
    for (int i = ty; i < 32; i += 8) {
        size_t oidx = ((size_t)bkv * HD + d0 + i) * SEQ + s0 + tx;
        outh[oidx] = __float2half_rn(tile[tx][i]);
    }
}

// ---------------- Flash attention: all single fp16, BM=128, Q in regs ------
#define QSTR 136
#define VSTR 72
#define KST  (64 * QSTR)
#define VST  (128 * VSTR)
#define STG_E (KST + VST)
#define OFF_V KST
#define FA_SMEM (3 * STG_E * 2)

__global__ void __launch_bounds__(256, 1) flash_mma(
        const __half* __restrict__ Qh, const __half* __restrict__ Kh,
        const __half* __restrict__ Vh, __half* __restrict__ Outh) {
    extern __shared__ __align__(16) __half fsm[];
    const uint32_t sbase = (uint32_t)__cvta_generic_to_shared(fsm);

    const int t = threadIdx.x, w = t >> 5, lane = t & 31;
    const int g = lane >> 2, tig = lane & 3;
    const int qb = gridDim.x - 1 - blockIdx.x;
    const int h = blockIdx.y, b = blockIdx.z;
    const int kvh = h >> 2;
    const int m0 = w * 16;
    const float SC2 = 0.08838834764831845f * 1.4426950408889634f;

    const __half* Qgh = Qh + ((size_t)(b * NH + h) * SEQ + qb * 128) * HD;
    const __half* Kbh = Kh + (size_t)(b * NKV + kvh) * SEQ * HD;
    const __half* Vbh = Vh + (size_t)(b * NKV + kvh) * HD * SEQ;

#pragma unroll
    for (int p = t; p < 128 * 16; p += 256) {
        int m = p >> 4, c8 = (p & 15) * 8;
        *(uint4*)&fsm[m * QSTR + c8] = *(const uint4*)(Qgh + (size_t)m * HD + c8);
    }
    __syncthreads();
    uint32_t qh[8][4];
#pragma unroll
    for (int kk = 0; kk < 8; kk++) {
        int rowA = m0 + (lane & 15);
        int colA = kk * 16 + ((lane >> 4) << 3);
        ldsm4(qh[kk], sbase + (uint32_t)(rowA * QSTR + colA) * 2);
    }
    __syncthreads();

    const int nt = 2 * qb + 2;

    auto issue = [&](int jt, int st) {
        const uint32_t base = sbase + (uint32_t)(st * STG_E) * 2;
        const __half* Kth = Kbh + (size_t)jt * 64 * HD;
        const __half* Vth = Vbh + jt * 64;
#pragma unroll
        for (int i = 0; i < 4; i++) {
            int c = t + 256 * i;
            int kr = c >> 4, kc8 = (c & 15) * 8;
            cpasync16(base + (uint32_t)(kr * QSTR + kc8) * 2, Kth + (size_t)kr * HD + kc8);
            int vd = c >> 3, vc8 = (c & 7) * 8;
            cpasync16(base + (uint32_t)(OFF_V + vd * VSTR + vc8) * 2, Vth + (size_t)vd * SEQ + vc8);
        }
        cp_commit();
    };

    float o[16][4];
#pragma unroll
    for (int nf = 0; nf < 16; nf++)
#pragma unroll
        for (int e = 0; e < 4; e++) o[nf][e] = 0.f;
    float mrun0 = -INFINITY, mrun1 = -INFINITY, lrun0 = 0.f, lrun1 = 0.f;

    issue(0, 0);
    if (nt > 1) issue(1, 1);

    int st3 = 2;
    for (int jt = 0; jt < nt; jt++) {
        if (jt + 1 < nt) cp_wait1(); else cp_wait0();
        __syncthreads();
        if (jt + 2 < nt) {
            issue(jt + 2, st3);
            if (++st3 == 3) st3 = 0;
        }
        const uint32_t base = sbase + (uint32_t)((jt % 3) * STG_E) * 2;

        float s[8][4];
#pragma unroll
        for (int nf = 0; nf < 8; nf++)
#pragma unroll
            for (int e = 0; e < 4; e++) s[nf][e] = 0.f;
#pragma unroll
        for (int kk = 0; kk < 8; kk++) {
#pragma unroll
            for (int jp = 0; jp < 4; jp += 2) {
                int rowB0 = jp * 16 + (lane & 7) + ((lane >> 4) & 1) * 8;
                int colB = kk * 16 + ((lane >> 3) & 1) * 8;
                uint32_t a0 = base + (uint32_t)(rowB0 * QSTR + colB) * 2;
                uint32_t a1 = a0 + (uint32_t)(16 * QSTR) * 2;
                uint32_t bh0[4], bh1[4];
                ldsm4(bh0, a0);
                ldsm4(bh1, a1);
                mma16(s[2 * jp],     qh[kk], bh0);
                mma16(s[2 * jp + 1], qh[kk], bh0 + 2);
                mma16(s[2 * jp + 2], qh[kk], bh1);
                mma16(s[2 * jp + 3], qh[kk], bh1 + 2);
            }
        }

        const int rowg = qb * 128 + m0 + g;
        const bool diag = (jt >= 2 * qb);
#pragma unroll
        for (int nf = 0; nf < 8; nf++) {
            int colb = jt * 64 + nf * 8 + 2 * tig;
#pragma unroll
            for (int e = 0; e < 4; e++) {
                float v = s[nf][e] * SC2;
                if (diag && (colb + (e & 1)) > (rowg + (e >> 1) * 8)) v = -1e30f;
                s[nf][e] = v;
            }
        }
        float ml0 = -INFINITY, ml1 = -INFINITY;
#pragma unroll
        for (int nf = 0; nf < 8; nf++) {
            ml0 = fmaxf(ml0, fmaxf(s[nf][0], s[nf][1]));
            ml1 = fmaxf(ml1, fmaxf(s[nf][2], s[nf][3]));
        }
        ml0 = fmaxf(ml0, __shfl_xor_sync(0xffffffffu, ml0, 1));
        ml0 = fmaxf(ml0, __shfl_xor_sync(0xffffffffu, ml0, 2));
        ml1 = fmaxf(ml1, __shfl_xor_sync(0xffffffffu, ml1, 1));
        ml1 = fmaxf(ml1, __shfl_xor_sync(0xffffffffu, ml1, 2));
        float mn0 = fmaxf(mrun0, ml0), mn1 = fmaxf(mrun1, ml1);
        float c0 = exp2f(mrun0 - mn0), c1 = exp2f(mrun1 - mn1);
        float ls0 = 0.f, ls1 = 0.f;
#pragma unroll
        for (int nf = 0; nf < 8; nf++) {
            s[nf][0] = exp2f(s[nf][0] - mn0);
            s[nf][1] = exp2f(s[nf][1] - mn0);
            s[nf][2] = exp2f(s[nf][2] - mn1);
            s[nf][3] = exp2f(s[nf][3] - mn1);
            ls0 += s[nf][0] + s[nf][1];
            ls1 += s[nf][2] + s[nf][3];
        }
        ls0 += __shfl_xor_sync(0xffffffffu, ls0, 1);
        ls0 += __shfl_xor_sync(0xffffffffu, ls0, 2);
        ls1 += __shfl_xor_sync(0xffffffffu, ls1, 1);
        ls1 += __shfl_xor_sync(0xffffffffu, ls1, 2);
        lrun0 = lrun0 * c0 + ls0;
        lrun1 = lrun1 * c1 + ls1;
        mrun0 = mn0; mrun1 = mn1;
        if (__any_sync(0xffffffffu, (c0 < 1.f) || (c1 < 1.f))) {
#pragma unroll
            for (int nf = 0; nf < 16; nf++) {
                o[nf][0] *= c0; o[nf][1] *= c0;
                o[nf][2] *= c1; o[nf][3] *= c1;
            }
        }

        uint32_t pah[4][4];
#pragma unroll
        for (int kk2 = 0; kk2 < 4; kk2++) {
            pah[kk2][0] = pack2h(s[2*kk2][0],   s[2*kk2][1]);
            pah[kk2][1] = pack2h(s[2*kk2][2],   s[2*kk2][3]);
            pah[kk2][2] = pack2h(s[2*kk2+1][0], s[2*kk2+1][1]);
            pah[kk2][3] = pack2h(s[2*kk2+1][2], s[2*kk2+1][3]);
        }

#pragma unroll
        for (int jp = 0; jp < 8; jp += 2) {
#pragma unroll
            for (int kk2 = 0; kk2 < 4; kk2++) {
                int rowB0 = jp * 16 + (lane & 7) + ((lane >> 4) & 1) * 8;
                int colB = kk2 * 16 + ((lane >> 3) & 1) * 8;
                uint32_t a0 = base + (uint32_t)(OFF_V + rowB0 * VSTR + colB) * 2;
                uint32_t a1 = a0 + (uint32_t)(16 * VSTR) * 2;
                uint32_t vh0[4], vh1[4];
                ldsm4(vh0, a0);
                ldsm4(vh1, a1);
                mma16(o[2 * jp],     pah[kk2], vh0);
                mma16(o[2 * jp + 1], pah[kk2], vh0 + 2);
                mma16(o[2 * jp + 2], pah[kk2], vh1);
                mma16(o[2 * jp + 3], pah[kk2], vh1 + 2);
            }
        }
    }

    float il0 = 1.f / lrun0, il1 = 1.f / lrun1;
    int qrow = qb * 128 + m0 + g;
    size_t base0 = (size_t)(b * SEQ + qrow) * (NH * HD) + h * HD;
    size_t base1 = base0 + (size_t)8 * (NH * HD);
#pragma unroll
    for (int nf = 0; nf < 16; nf++) {
        *(uint32_t*)(Outh + base0 + nf * 8 + 2 * tig) = pack2h(o[nf][0] * il0, o[nf][1] * il0);
        *(uint32_t*)(Outh + base1 + nf * 8 + 2 * tig) = pack2h(o[nf][2] * il1, o[nf][3] * il1);
    }
}

// ---------------- launch -----------------------------------------------------
extern "C" void kernel_launch(void* const* d_in, const int* in_sizes, int n_in,
                              void* d_out, int out_size) {
    (void)in_sizes; (void)n_in; (void)out_size;
    const float* x  = (const float*)d_in[0];
    const float* Wq = (const float*)d_in[1];
    const float* Wk = (const float*)d_in[2];
    const float* Wv = (const float*)d_in[3];
    const float* Wo = (const float*)d_in[4];
    const float* qg = (const float*)d_in[5];
    const float* kg = (const float*)d_in[6];
    const float* cs = (const float*)d_in[7];
    const float* sn = (const float*)d_in[8];
    float* out = (float*)d_out;

    float* qkvb;
    __half *xh, *attnh, *qkvWh, *WoTh, *Qh, *Kh, *Vh;
    cudaGetSymbolAddress((void**)&qkvb,  g_qkv);
    cudaGetSymbolAddress((void**)&xh,    g_xh);
    cudaGetSymbolAddress((void**)&attnh, g_attnh);
    cudaGetSymbolAddress((void**)&qkvWh, g_qkvWh);
    cudaGetSymbolAddress((void**)&WoTh,  g_WoTh);
    cudaGetSymbolAddress((void**)&Qh,    g_Qh);
    cudaGetSymbolAddress((void**)&Kh,    g_Kh);
    cudaGetSymbolAddress((void**)&Vh,    g_Vh);

    const int M = BATCH * SEQ;  // 4096

    cudaFuncSetAttribute(gemm_h,    cudaFuncAttributeMaxDynamicSharedMemorySize, GEMM_SMEM);
    cudaFuncSetAttribute(flash_mma, cudaFuncAttributeMaxDynamicSharedMemorySize, FA_SMEM);

    convert_half<<<(M * DIMC / 4 + 255) / 256, 256>>>(x, xh, M * DIMC / 4);
    transpose_half<<<dim3(DIMC / 32, DIMC / 32), 256>>>(Wq, qkvWh, DIMC, DIMC);
    transpose_half2<<<dim3((NKV * HD) / 32, DIMC / 32, 2), 256>>>(
        Wk, Wv, qkvWh + (size_t)2048 * DIMC, qkvWh + (size_t)2560 * DIMC,
        DIMC, NKV * HD);
    gemm_h<<<dim3(QKVW / 128, M / 128), 256, GEMM_SMEM>>>(
        xh, qkvWh, qkvb, QKVW, DIMC);
    transpose_half<<<dim3(DIMC / 32, DIMC / 32), 256>>>(Wo, WoTh, DIMC, DIMC);

    rmsnorm_rope_k<<<(M * NH)  / 8, 256>>>(qkvb, QKVW, qg, cs, sn, Qh, NH,  M * NH);
    rmsnorm_rope_k<<<(M * NKV) / 8, 256>>>(qkvb + 2048, QKVW, kg, cs, sn, Kh, NKV, M * NKV);
    vtrans_k<<<dim3(SEQ / 32, HD / 32, BATCH * NKV), 256>>>(qkvb + 2560, Vh);

    flash_mma<<<dim3(SEQ / 128, NH, BATCH), 256, FA_SMEM>>>(Qh, Kh, Vh, attnh);

    gemm_h<<<dim3(DIMC / 128, M / 128), 256, GEMM_SMEM>>>(
        attnh, WoTh, out, DIMC, DIMC);
}